// round 13
// baseline (speedup 1.0000x reference)
#include <cuda_runtime.h>
#include <math.h>
#include <stdint.h>

// ---------------- Problem constants ----------------
#define NHEAD 16
#define HS    64
#define NLM   64
#define TLEN  4096
#define BATCH 4
#define BH    64
#define CDIM  1024
#define HEAD_ELEMS (TLEN*HS)
#define QKV_ELEMS  (BH*HEAD_ELEMS)
#define SSTR  65

// ---------------- Scratch ----------------
__device__ float g_Q[QKV_ELEMS];
__device__ float g_K[QKV_ELEMS];
__device__ float g_V[QKV_ELEMS];
__device__ float g_ql[BH*NLM*HS];
__device__ float g_kl[BH*NLM*HS];
__device__ float g_P [BH*NLM*NLM];
__device__ float g_NVp[BH*8*NLM*HS];
__device__ float g_mp [BH*8*NLM];
__device__ float g_sp [BH*8*NLM];
__device__ float g_NV [BH*NLM*HS];
__device__ float g_Z  [BH*NLM*HS];
__device__ float g_Y  [BATCH*TLEN*CDIM];   // tf32-rounded, k-permuted (GEMM2 A)
__device__ float g_X  [BATCH*TLEN*CDIM];   // tf32-rounded, k-permuted (GEMM1 A)
__device__ float g_WaT[3*CDIM*CDIM];       // W_attn^T [n][k], tf32-rounded, k-permuted
__device__ float g_WpT[CDIM*CDIM];         // W_proj^T [n][k], tf32-rounded, k-permuted

// ======================= tf32 helpers ======================================
__device__ __forceinline__ uint32_t f2tf32(float x) {
  uint32_t u;
  asm("cvt.rna.tf32.f32 %0, %1;" : "=r"(u) : "f"(x));
  return u;
}
__device__ __forceinline__ void mma_tf32(float c[4], uint32_t a0, uint32_t a1,
                                         uint32_t a2, uint32_t a3,
                                         uint32_t b0, uint32_t b1) {
  asm volatile(
    "mma.sync.aligned.m16n8k8.row.col.f32.tf32.tf32.f32 "
    "{%0,%1,%2,%3}, {%4,%5,%6,%7}, {%8,%9}, {%0,%1,%2,%3};"
    : "+f"(c[0]), "+f"(c[1]), "+f"(c[2]), "+f"(c[3])
    : "r"(a0), "r"(a1), "r"(a2), "r"(a3), "r"(b0), "r"(b1));
}
__device__ __forceinline__ void cp_async16(void* smem_dst, const void* gsrc) {
  uint32_t s = (uint32_t)__cvta_generic_to_shared(smem_dst);
  asm volatile("cp.async.ca.shared.global [%0], [%1], 16;\n" :: "r"(s), "l"(gsrc));
}
#define CP_COMMIT() asm volatile("cp.async.commit_group;\n" ::: "memory")
#define CP_WAIT(n)  asm volatile("cp.async.wait_group %0;\n" :: "n"(n) : "memory")

// ---------------- pre-round + k-group permute (for A inputs) ----------------
__global__ __launch_bounds__(256) void round_permute_kernel(const float4* __restrict__ src,
                                                            float4* __restrict__ dst, int n8) {
  int i = blockIdx.x * blockDim.x + threadIdx.x;
  if (i < n8) {
    float4 v0 = src[2*i];
    float4 v1 = src[2*i + 1];
    float4 w0, w1;
    w0.x = __uint_as_float(f2tf32(v0.x));
    w0.y = __uint_as_float(f2tf32(v1.x));
    w0.z = __uint_as_float(f2tf32(v0.y));
    w0.w = __uint_as_float(f2tf32(v1.y));
    w1.x = __uint_as_float(f2tf32(v0.z));
    w1.y = __uint_as_float(f2tf32(v1.z));
    w1.z = __uint_as_float(f2tf32(v0.w));
    w1.w = __uint_as_float(f2tf32(v1.w));
    dst[2*i] = w0;
    dst[2*i + 1] = w1;
  }
}

// ---------------- transpose + round + k-permute (for B weights) ------------
__global__ __launch_bounds__(256) void transpose_rp_kernel(const float* __restrict__ src,
                                                           float* __restrict__ dst, int ND) {
  __shared__ float t[32][33];
  const int KD = 1024;
  int n0 = blockIdx.x * 32, k0 = blockIdx.y * 32;
  int tx = threadIdx.x & 31, ty8 = threadIdx.x >> 5;
#pragma unroll
  for (int r = 0; r < 4; r++) {
    int k = k0 + ty8 + r*8;
    t[ty8 + r*8][tx] = __uint_as_float(f2tf32(src[(size_t)k*ND + n0 + tx]));
  }
  __syncthreads();
#pragma unroll
  for (int r = 0; r < 4; r++) {
    int n = n0 + ty8 + r*8;
    int c = tx & 7;
    int kpos = (tx & ~7) + 2*(c & 3) + (c >> 2);
    dst[(size_t)n*KD + k0 + kpos] = t[tx][ty8 + r*8];
  }
}

// ---------------- GEMM: 128x128 tile, 8 warps (2x4) at 64x32, float2 frags -
// Register-relieved: acc=64/thread -> 2 CTAs x 256thr = 16 warps/SM.
// Single __syncthreads per k-chunk (R11 pipeline).
#define TSTR 40
#define T_BUF (128*TSTR)
#define GEMM_SMEM (4*T_BUF*4)

template <int N, int MODE>
__global__ __launch_bounds__(256, 2) void gemm_tf32(float* __restrict__ Cout) {
  extern __shared__ float sm[];
  float* As[2] = { sm,           sm + T_BUF };
  float* Bs[2] = { sm + 2*T_BUF, sm + 3*T_BUF };

  const float* A  = (MODE == 1) ? (const float*)g_X   : (const float*)g_Y;
  const float* Bt = (MODE == 1) ? (const float*)g_WaT : (const float*)g_WpT;

  const int K = 1024;
  const int tid = threadIdx.x;
  const int warp = tid >> 5, lane = tid & 31;
  const int wm = warp >> 2, wn = warp & 3;        // warp grid 2x4
  const int g = lane >> 2, tg = lane & 3;

  const float* Ap = A  + (size_t)(blockIdx.y * 128) * K;
  const float* Bp = Bt + (size_t)(blockIdx.x * 128) * K;

  float acc[4][4][4];                              // 64 regs
#pragma unroll
  for (int i = 0; i < 4; i++)
#pragma unroll
    for (int j = 0; j < 4; j++)
#pragma unroll
      for (int r = 0; r < 4; r++) acc[i][j][r] = 0.f;

  const int cr = tid >> 3;            // 0..31
  const int cs = (tid & 7) * 4;

  auto load_tile = [&](int kt, int buf) {
    const int k0 = kt * 32;
#pragma unroll
    for (int i = 0; i < 4; i++) {
      int row = cr + i * 32;
      cp_async16(As[buf] + row*TSTR + cs, Ap + (size_t)row * K + k0 + cs);
      cp_async16(Bs[buf] + row*TSTR + cs, Bp + (size_t)row * K + k0 + cs);
    }
    CP_COMMIT();
  };

  load_tile(0, 0);
  const int NT = K / 32;
  for (int kt = 0; kt < NT; kt++) {
    CP_WAIT(0);
    __syncthreads();
    if (kt + 1 < NT) load_tile(kt + 1, (kt + 1) & 1);
    const float* Ab = As[kt & 1];
    const float* Bb = Bs[kt & 1];
#pragma unroll
    for (int ks = 0; ks < 4; ks++) {
      const int kp = ks * 8 + 2 * tg;
      uint32_t bf[4][2];
#pragma unroll
      for (int nt = 0; nt < 4; nt++) {
        int nb = wn * 32 + nt * 8 + g;
        float2 b2 = *(const float2*)&Bb[nb * TSTR + kp];
        bf[nt][0] = __float_as_uint(b2.x);
        bf[nt][1] = __float_as_uint(b2.y);
      }
#pragma unroll
      for (int mt = 0; mt < 4; mt++) {
        int rm = wm * 64 + mt * 16;
        float2 alo = *(const float2*)&Ab[(rm + g    ) * TSTR + kp];
        float2 ahi = *(const float2*)&Ab[(rm + g + 8) * TSTR + kp];
        uint32_t a0 = __float_as_uint(alo.x);
        uint32_t a1 = __float_as_uint(ahi.x);
        uint32_t a2 = __float_as_uint(alo.y);
        uint32_t a3 = __float_as_uint(ahi.y);
#pragma unroll
        for (int nt = 0; nt < 4; nt++)
          mma_tf32(acc[mt][nt], a0, a1, a2, a3, bf[nt][0], bf[nt][1]);
      }
    }
  }

#pragma unroll
  for (int mt = 0; mt < 4; mt++) {
#pragma unroll
    for (int nt = 0; nt < 4; nt++) {
      int row = blockIdx.y * 128 + wm * 64 + mt * 16 + g;
      int col = blockIdx.x * 128 + wn * 32 + nt * 8 + 2 * tg;
      if (MODE == 0) {
        float* p0 = Cout + (size_t)row * N + col;
        float* p1 = Cout + (size_t)(row + 8) * N + col;
        *(float2*)p0 = make_float2(acc[mt][nt][0], acc[mt][nt][1]);
        *(float2*)p1 = make_float2(acc[mt][nt][2], acc[mt][nt][3]);
      } else {
        int which = col >> 10;
        int h = (col >> 6) & 15, d = col & 63;
        float* dst = (which == 0) ? g_Q : ((which == 1) ? g_K : g_V);
        int b0 = row >> 12, t0 = row & 4095;
        float* p0 = dst + ((size_t)((b0 * NHEAD + h) * TLEN + t0)) * HS + d;
        int rowb = row + 8;
        int b1 = rowb >> 12, t1 = rowb & 4095;
        float* p1 = dst + ((size_t)((b1 * NHEAD + h) * TLEN + t1)) * HS + d;
        *(float2*)p0 = make_float2(acc[mt][nt][0], acc[mt][nt][1]);
        *(float2*)p1 = make_float2(acc[mt][nt][2], acc[mt][nt][3]);
      }
    }
  }
}

// ---------------- 64x64 tile helpers: strided ownership ----------
__device__ __forceinline__ void mm_regs_AB(float acc[4][4], const float* __restrict__ A,
                                           const float* __restrict__ B, int ty, int tx) {
#pragma unroll
  for (int i = 0; i < 4; i++)
#pragma unroll
    for (int j = 0; j < 4; j++) acc[i][j] = 0.f;
  for (int k = 0; k < 64; k++) {
    float a0 = A[(ty   )*SSTR+k], a1 = A[(ty+16)*SSTR+k];
    float a2 = A[(ty+32)*SSTR+k], a3 = A[(ty+48)*SSTR+k];
    float b0 = B[k*SSTR+tx   ], b1 = B[k*SSTR+tx+16];
    float b2 = B[k*SSTR+tx+32], b3 = B[k*SSTR+tx+48];
    acc[0][0]=fmaf(a0,b0,acc[0][0]); acc[0][1]=fmaf(a0,b1,acc[0][1]);
    acc[0][2]=fmaf(a0,b2,acc[0][2]); acc[0][3]=fmaf(a0,b3,acc[0][3]);
    acc[1][0]=fmaf(a1,b0,acc[1][0]); acc[1][1]=fmaf(a1,b1,acc[1][1]);
    acc[1][2]=fmaf(a1,b2,acc[1][2]); acc[1][3]=fmaf(a1,b3,acc[1][3]);
    acc[2][0]=fmaf(a2,b0,acc[2][0]); acc[2][1]=fmaf(a2,b1,acc[2][1]);
    acc[2][2]=fmaf(a2,b2,acc[2][2]); acc[2][3]=fmaf(a2,b3,acc[2][3]);
    acc[3][0]=fmaf(a3,b0,acc[3][0]); acc[3][1]=fmaf(a3,b1,acc[3][1]);
    acc[3][2]=fmaf(a3,b2,acc[3][2]); acc[3][3]=fmaf(a3,b3,acc[3][3]);
  }
}
__device__ __forceinline__ void mm_acc_AB(float acc[4][4], const float* __restrict__ A,
                                          const float* __restrict__ B, int ty, int tx) {
  for (int k = 0; k < 64; k++) {
    float a0 = A[(ty   )*SSTR+k], a1 = A[(ty+16)*SSTR+k];
    float a2 = A[(ty+32)*SSTR+k], a3 = A[(ty+48)*SSTR+k];
    float b0 = B[k*SSTR+tx   ], b1 = B[k*SSTR+tx+16];
    float b2 = B[k*SSTR+tx+32], b3 = B[k*SSTR+tx+48];
    acc[0][0]=fmaf(a0,b0,acc[0][0]); acc[0][1]=fmaf(a0,b1,acc[0][1]);
    acc[0][2]=fmaf(a0,b2,acc[0][2]); acc[0][3]=fmaf(a0,b3,acc[0][3]);
    acc[1][0]=fmaf(a1,b0,acc[1][0]); acc[1][1]=fmaf(a1,b1,acc[1][1]);
    acc[1][2]=fmaf(a1,b2,acc[1][2]); acc[1][3]=fmaf(a1,b3,acc[1][3]);
    acc[2][0]=fmaf(a2,b0,acc[2][0]); acc[2][1]=fmaf(a2,b1,acc[2][1]);
    acc[2][2]=fmaf(a2,b2,acc[2][2]); acc[2][3]=fmaf(a2,b3,acc[2][3]);
    acc[3][0]=fmaf(a3,b0,acc[3][0]); acc[3][1]=fmaf(a3,b1,acc[3][1]);
    acc[3][2]=fmaf(a3,b2,acc[3][2]); acc[3][3]=fmaf(a3,b3,acc[3][3]);
  }
}
__device__ __forceinline__ void mm_regs_ABt(float acc[4][4], const float* __restrict__ A,
                                            const float* __restrict__ B, int ty, int tx) {
#pragma unroll
  for (int i = 0; i < 4; i++)
#pragma unroll
    for (int j = 0; j < 4; j++) acc[i][j] = 0.f;
  for (int d = 0; d < 64; d++) {
    float a0 = A[(ty   )*SSTR+d], a1 = A[(ty+16)*SSTR+d];
    float a2 = A[(ty+32)*SSTR+d], a3 = A[(ty+48)*SSTR+d];
    float b0 = B[(tx   )*SSTR+d], b1 = B[(tx+16)*SSTR+d];
    float b2 = B[(tx+32)*SSTR+d], b3 = B[(tx+48)*SSTR+d];
    acc[0][0]=fmaf(a0,b0,acc[0][0]); acc[0][1]=fmaf(a0,b1,acc[0][1]);
    acc[0][2]=fmaf(a0,b2,acc[0][2]); acc[0][3]=fmaf(a0,b3,acc[0][3]);
    acc[1][0]=fmaf(a1,b0,acc[1][0]); acc[1][1]=fmaf(a1,b1,acc[1][1]);
    acc[1][2]=fmaf(a1,b2,acc[1][2]); acc[1][3]=fmaf(a1,b3,acc[1][3]);
    acc[2][0]=fmaf(a2,b0,acc[2][0]); acc[2][1]=fmaf(a2,b1,acc[2][1]);
    acc[2][2]=fmaf(a2,b2,acc[2][2]); acc[2][3]=fmaf(a2,b3,acc[2][3]);
    acc[3][0]=fmaf(a3,b0,acc[3][0]); acc[3][1]=fmaf(a3,b1,acc[3][1]);
    acc[3][2]=fmaf(a3,b2,acc[3][2]); acc[3][3]=fmaf(a3,b3,acc[3][3]);
  }
}
__device__ __forceinline__ void mm_store_AB(float* __restrict__ C, const float* __restrict__ A,
                                            const float* __restrict__ B, int ty, int tx) {
  float acc[4][4];
  mm_regs_AB(acc, A, B, ty, tx);
#pragma unroll
  for (int i = 0; i < 4; i++)
#pragma unroll
    for (int j = 0; j < 4; j++) C[(ty+16*i)*SSTR + tx + 16*j] = acc[i][j];
}
__device__ __forceinline__ float rowmax16(float v) {
#pragma unroll
  for (int off = 8; off; off >>= 1)
    v = fmaxf(v, __shfl_xor_sync(0xffffffffu, v, off, 16));
  return v;
}
__device__ __forceinline__ float rowsum16(float v) {
#pragma unroll
  for (int off = 8; off; off >>= 1)
    v += __shfl_xor_sync(0xffffffffu, v, off, 16);
  return v;
}

// ---------------- Landmarks ----------------
__global__ void landmarks_kernel() {
  const int bh = blockIdx.y, l = blockIdx.x, d = threadIdx.x;
  const float* qb = g_Q + (size_t)bh * HEAD_ELEMS + (size_t)l * 64 * HS;
  const float* kb = g_K + (size_t)bh * HEAD_ELEMS + (size_t)l * 64 * HS;
  float sq = 0.f, sk = 0.f;
  for (int tt = 0; tt < 64; tt++) { sq += qb[tt*HS + d]; sk += kb[tt*HS + d]; }
  g_ql[bh*NLM*HS + l*HS + d] = sq * (1.f/64.f);
  g_kl[bh*NLM*HS + l*HS + d] = sk * (1.f/64.f);
}

// ---------------- Newton-Schulz ----------------
__global__ __launch_bounds__(256) void ns_kernel() {
  extern __shared__ float sm[];
  float* sK  = sm;
  float* sV  = sm + 4160;
  float* sKV = sm + 2*4160;
  float* sT  = sm + 3*4160;
  float* sU  = sm + 4*4160;
  __shared__ float scol[64];
  __shared__ float sden;
  const int bh = blockIdx.x;
  const int tid = threadIdx.x;
  const int ty = tid >> 4, tx = tid & 15;

  for (int e = tid; e < 4096; e += 256) {
    int l = e >> 6, d = e & 63;
    sT[l*SSTR + d] = g_ql[bh*4096 + e];
    sU[l*SSTR + d] = g_kl[bh*4096 + e];
  }
  __syncthreads();
  {
    float acc[4][4];
    mm_regs_ABt(acc, sT, sU, ty, tx);
#pragma unroll
    for (int i = 0; i < 4; i++)
#pragma unroll
      for (int j = 0; j < 4; j++) sK[(ty+16*i)*SSTR + tx + 16*j] = acc[i][j];
  }
  __syncthreads();
  if (tid < 64) {
    float m = -1e30f;
    for (int j = 0; j < 64; j++) m = fmaxf(m, sK[tid*SSTR + j]);
    float s = 0.f;
    for (int j = 0; j < 64; j++) { float e_ = expf(sK[tid*SSTR + j] - m); sK[tid*SSTR + j] = e_; s += e_; }
    float inv = 1.f / s;
    for (int j = 0; j < 64; j++) sK[tid*SSTR + j] *= inv;
  }
  __syncthreads();
  if (tid < 64) {
    float cs = 0.f;
    for (int i = 0; i < 64; i++) cs += sK[i*SSTR + tid];
    scol[tid] = cs;
  }
  __syncthreads();
  if (tid == 0) {
    float mx = scol[0];
    for (int j = 1; j < 64; j++) mx = fmaxf(mx, scol[j]);
    sden = mx;
  }
  __syncthreads();
  const float invden = 1.f / sden;
  for (int e = tid; e < 4096; e += 256) {
    int i = e >> 6, j = e & 63;
    sV[i*SSTR + j] = sK[j*SSTR + i] * invden;
  }
  __syncthreads();
  for (int it = 0; it < 6; it++) {
    mm_store_AB(sKV, sK, sV, ty, tx); __syncthreads();
    for (int e = tid; e < 4096; e += 256) {
      int i = e >> 6, j = e & 63;
      sT[i*SSTR + j] = ((i == j) ? 7.f : 0.f) - sKV[i*SSTR + j];
    }
    __syncthreads();
    mm_store_AB(sU, sKV, sT, ty, tx); __syncthreads();
    for (int e = tid; e < 4096; e += 256) {
      int i = e >> 6, j = e & 63;
      sT[i*SSTR + j] = ((i == j) ? 15.f : 0.f) - sU[i*SSTR + j];
    }
    __syncthreads();
    mm_store_AB(sU, sKV, sT, ty, tx); __syncthreads();
    for (int e = tid; e < 4096; e += 256) {
      int i = e >> 6, j = e & 63;
      sT[i*SSTR + j] = ((i == j) ? 13.f : 0.f) - sU[i*SSTR + j];
    }
    __syncthreads();
    mm_store_AB(sU, sV, sT, ty, tx); __syncthreads();
    for (int e = tid; e < 4096; e += 256) {
      int i = e >> 6, j = e & 63;
      sV[i*SSTR + j] = 0.25f * sU[i*SSTR + j];
    }
    __syncthreads();
  }
  for (int e = tid; e < 4096; e += 256) {
    int l = e >> 6, d = e & 63;
    g_P[bh*4096 + e] = sV[l*SSTR + d];
  }
}

// ---------------- NV partial ----------------
__global__ __launch_bounds__(256) void nv_partial() {
  extern __shared__ float sm[];
  float* sql = sm;
  float* skP = sm + 4160;
  float* sv  = sm + 2*4160;
  const int bh = blockIdx.y, ts = blockIdx.x;
  const int tid = threadIdx.x, ty = tid >> 4, tx = tid & 15;
  const float* Kb = g_K + (size_t)bh * HEAD_ELEMS;
  const float* Vb = g_V + (size_t)bh * HEAD_ELEMS;

  for (int e = tid; e < 4096; e += 256)
    sql[(e >> 6)*SSTR + (e & 63)] = g_ql[bh*4096 + e];

  float rowm[4], rsum[4], acc[4][4];
#pragma unroll
  for (int i = 0; i < 4; i++) {
    rowm[i] = -1e30f; rsum[i] = 0.f;
#pragma unroll
    for (int j = 0; j < 4; j++) acc[i][j] = 0.f;
  }
  __syncthreads();
  const int tbase = ts * 512;
  for (int c = 0; c < 8; c++) {
    const int t0 = tbase + c * 64;
    for (int e = tid; e < 4096; e += 256) {
      skP[(e >> 6)*SSTR + (e & 63)] = Kb[(size_t)t0 * 64 + e];
      sv [(e >> 6)*SSTR + (e & 63)] = Vb[(size_t)t0 * 64 + e];
    }
    __syncthreads();
    float s[4][4];
    mm_regs_ABt(s, sql, skP, ty, tx);
#pragma unroll
    for (int i = 0; i < 4; i++) {
      float mx = fmaxf(fmaxf(s[i][0], s[i][1]), fmaxf(s[i][2], s[i][3]));
      mx = rowmax16(mx);
      float nm = fmaxf(rowm[i], mx);
      float al = expf(rowm[i] - nm);
      rowm[i] = nm;
#pragma unroll
      for (int j = 0; j < 4; j++) s[i][j] = expf(s[i][j] - nm);
      float ls = s[i][0] + s[i][1] + s[i][2] + s[i][3];
      ls = rowsum16(ls);
      rsum[i] = rsum[i] * al + ls;
#pragma unroll
      for (int j = 0; j < 4; j++) acc[i][j] *= al;
    }
    __syncthreads();
#pragma unroll
    for (int i = 0; i < 4; i++)
#pragma unroll
      for (int j = 0; j < 4; j++) skP[(ty+16*i)*SSTR + tx + 16*j] = s[i][j];
    __syncthreads();
    mm_acc_AB(acc, skP, sv, ty, tx);
    __syncthreads();
  }
  const size_t pb = (size_t)(bh*8 + ts) * 4096;
#pragma unroll
  for (int i = 0; i < 4; i++)
#pragma unroll
    for (int j = 0; j < 4; j++)
      g_NVp[pb + (ty+16*i)*64 + tx + 16*j] = acc[i][j];
  if (tx == 0) {
#pragma unroll
    for (int i = 0; i < 4; i++) {
      g_mp[(bh*8 + ts)*64 + ty + 16*i] = rowm[i];
      g_sp[(bh*8 + ts)*64 + ty + 16*i] = rsum[i];
    }
  }
}

// ---------------- Combine ----------------
__global__ __launch_bounds__(256) void nv_combine() {
  const int bh = blockIdx.x, tid = threadIdx.x;
  __shared__ float W[8][64];
  __shared__ float D[64];
  if (tid < 64) {
    float mp[8];
    float m = -1e30f;
    for (int p = 0; p < 8; p++) { mp[p] = g_mp[(bh*8 + p)*64 + tid]; m = fmaxf(m, mp[p]); }
    float dd = 0.f;
    for (int p = 0; p < 8; p++) {
      float w = expf(mp[p] - m);
      W[p][tid] = w;
      dd += g_sp[(bh*8 + p)*64 + tid] * w;
    }
    D[tid] = dd;
  }
  __syncthreads();
  for (int e = tid; e < 4096; e += 256) {
    int l = e >> 6;
    float v = 0.f;
    for (int p = 0; p < 8; p++)
      v += g_NVp[(size_t)(bh*8 + p)*4096 + e] * W[p][l];
    g_NV[bh*4096 + e] = v / D[l];
  }
}

// ---------------- Z = P @ NV ----------------
__global__ __launch_bounds__(256) void z_kernel() {
  __shared__ float sA[64*SSTR];
  __shared__ float sB[64*SSTR];
  const int bh = blockIdx.x, tid = threadIdx.x;
  const int ty = tid >> 4, tx = tid & 15;
  for (int e = tid; e < 4096; e += 256) {
    int l = e >> 6, d = e & 63;
    sA[l*SSTR + d] = g_P [bh*4096 + e];
    sB[l*SSTR + d] = g_NV[bh*4096 + e];
  }
  __syncthreads();
  float acc[4][4];
  mm_regs_AB(acc, sA, sB, ty, tx);
#pragma unroll
  for (int i = 0; i < 4; i++)
#pragma unroll
    for (int j = 0; j < 4; j++)
      g_Z[bh*4096 + (ty+16*i)*64 + tx + 16*j] = acc[i][j];
}

// ---------------- Y = softmax(q @ k_l^T) @ Z, rounded + k-permuted ---------
__global__ __launch_bounds__(256) void ly_kernel() {
  extern __shared__ float sm[];
  float* sqP = sm;
  float* skl = sm + 4160;
  float* sZ  = sm + 2*4160;
  const int bh = blockIdx.y, tt = blockIdx.x;
  const int tid = threadIdx.x, ty = tid >> 4, tx = tid & 15;
  const int t0 = tt * 64;
  const float* Qb = g_Q + (size_t)bh * HEAD_ELEMS + (size_t)t0 * 64;
  for (int e = tid; e < 4096; e += 256) {
    int l = e >> 6, d = e & 63;
    sqP[l*SSTR + d] = Qb[e];
    skl[l*SSTR + d] = g_kl[bh*4096 + e];
    sZ [l*SSTR + d] = g_Z [bh*4096 + e];
  }
  __syncthreads();
  float s[4][4];
  mm_regs_ABt(s, sqP, skl, ty, tx);
  float rs[4];
#pragma unroll
  for (int i = 0; i < 4; i++) {
    float mx = fmaxf(fmaxf(s[i][0], s[i][1]), fmaxf(s[i][2], s[i][3]));
    mx = rowmax16(mx);
#pragma unroll
    for (int j = 0; j < 4; j++) s[i][j] = expf(s[i][j] - mx);
    float ls = s[i][0] + s[i][1] + s[i][2] + s[i][3];
    rs[i] = rowsum16(ls);
  }
  __syncthreads();
#pragma unroll
  for (int i = 0; i < 4; i++)
#pragma unroll
    for (int j = 0; j < 4; j++) sqP[(ty+16*i)*SSTR + tx + 16*j] = s[i][j];
  __syncthreads();
  float acc[4][4];
  mm_regs_AB(acc, sqP, sZ, ty, tx);
  const int b = bh >> 4, h = bh & 15;
  const int w = tx & 7;
  const int cbase = h*HS + (tx & ~7) + 2*(w & 3) + (w >> 2);
#pragma unroll
  for (int i = 0; i < 4; i++) {
    float inv = 1.f / rs[i];
    float* prow = g_Y + (size_t)(b*TLEN + t0 + ty + 16*i) * CDIM;
#pragma unroll
    for (int j = 0; j < 4; j++) {
      float v = __uint_as_float(f2tf32(acc[i][j] * inv));
      prow[cbase + 16*j] = v;
    }
  }
}

// ---------------- Launch ----------------
extern "C" void kernel_launch(void* const* d_in, const int* in_sizes, int n_in,
                              void* d_out, int out_size) {
  const float* x  = (const float*)d_in[0];
  const float* Wa = (const float*)d_in[1];
  const float* Wp = (const float*)d_in[2];
  float* out = (float*)d_out;

  const int smem5 = 5 * 4160 * 4;
  const int smem3 = 3 * 4160 * 4;
  cudaFuncSetAttribute(ns_kernel,  cudaFuncAttributeMaxDynamicSharedMemorySize, smem5);
  cudaFuncSetAttribute(nv_partial, cudaFuncAttributeMaxDynamicSharedMemorySize, smem3);
  cudaFuncSetAttribute(ly_kernel,  cudaFuncAttributeMaxDynamicSharedMemorySize, smem3);
  cudaFuncSetAttribute((const void*)gemm_tf32<3072,1>, cudaFuncAttributeMaxDynamicSharedMemorySize, GEMM_SMEM);
  cudaFuncSetAttribute((const void*)gemm_tf32<1024,0>, cudaFuncAttributeMaxDynamicSharedMemorySize, GEMM_SMEM);

  float* dX;  cudaGetSymbolAddress((void**)&dX,  g_X);
  float* dWaT; cudaGetSymbolAddress((void**)&dWaT, g_WaT);
  float* dWpT; cudaGetSymbolAddress((void**)&dWpT, g_WpT);
  round_permute_kernel<<<(BATCH*TLEN*CDIM/8 + 255)/256, 256>>>((const float4*)x, (float4*)dX, BATCH*TLEN*CDIM/8);
  transpose_rp_kernel<<<dim3(3*CDIM/32, CDIM/32), 256>>>(Wa, dWaT, 3*CDIM);
  transpose_rp_kernel<<<dim3(CDIM/32, CDIM/32), 256>>>(Wp, dWpT, CDIM);

  gemm_tf32<3072,1><<<dim3(24, 128), 256, GEMM_SMEM>>>(nullptr);
  landmarks_kernel<<<dim3(NLM, BH), 64>>>();
  ns_kernel<<<BH, 256, smem5>>>();
  nv_partial<<<dim3(8, BH), 256, smem3>>>();
  nv_combine<<<BH, 256>>>();
  z_kernel<<<BH, 256>>>();
  ly_kernel<<<dim3(64, BH), 256, smem3>>>();
  gemm_tf32<1024,0><<<dim3(8, 128), 256, GEMM_SMEM>>>(out);
}

// round 14
// speedup vs baseline: 1.1155x; 1.1155x over previous
#include <cuda_runtime.h>
#include <math.h>
#include <stdint.h>

// ---------------- Problem constants ----------------
#define NHEAD 16
#define HS    64
#define NLM   64
#define TLEN  4096
#define BATCH 4
#define BH    64
#define CDIM  1024
#define HEAD_ELEMS (TLEN*HS)
#define QKV_ELEMS  (BH*HEAD_ELEMS)
#define SSTR  65

// ---------------- Scratch ----------------
__device__ float g_Q[QKV_ELEMS];
__device__ float g_K[QKV_ELEMS];
__device__ float g_V[QKV_ELEMS];
__device__ float g_ql[BH*NLM*HS];
__device__ float g_kl[BH*NLM*HS];
__device__ float g_P [BH*NLM*NLM];
__device__ float g_NVp[BH*8*NLM*HS];
__device__ float g_mp [BH*8*NLM];
__device__ float g_sp [BH*8*NLM];
__device__ float g_Z  [BH*NLM*HS];
__device__ float g_Y  [BATCH*TLEN*CDIM];   // tf32-rounded, k-permuted (GEMM2 A)
__device__ float g_X  [BATCH*TLEN*CDIM];   // tf32-rounded, k-permuted (GEMM1 A)
__device__ float g_WaT[3*CDIM*CDIM];       // W_attn^T [n][k], tf32-rounded, k-permuted
__device__ float g_WpT[CDIM*CDIM];         // W_proj^T [n][k], tf32-rounded, k-permuted

// ======================= tf32 helpers ======================================
__device__ __forceinline__ uint32_t f2tf32(float x) {
  uint32_t u;
  asm("cvt.rna.tf32.f32 %0, %1;" : "=r"(u) : "f"(x));
  return u;
}
__device__ __forceinline__ void mma_tf32(float c[4], uint32_t a0, uint32_t a1,
                                         uint32_t a2, uint32_t a3,
                                         uint32_t b0, uint32_t b1) {
  asm volatile(
    "mma.sync.aligned.m16n8k8.row.col.f32.tf32.tf32.f32 "
    "{%0,%1,%2,%3}, {%4,%5,%6,%7}, {%8,%9}, {%0,%1,%2,%3};"
    : "+f"(c[0]), "+f"(c[1]), "+f"(c[2]), "+f"(c[3])
    : "r"(a0), "r"(a1), "r"(a2), "r"(a3), "r"(b0), "r"(b1));
}
__device__ __forceinline__ void cp_async16(void* smem_dst, const void* gsrc) {
  uint32_t s = (uint32_t)__cvta_generic_to_shared(smem_dst);
  asm volatile("cp.async.ca.shared.global [%0], [%1], 16;\n" :: "r"(s), "l"(gsrc));
}
#define CP_COMMIT() asm volatile("cp.async.commit_group;\n" ::: "memory")
#define CP_WAIT(n)  asm volatile("cp.async.wait_group %0;\n" :: "n"(n) : "memory")

// ---------------- pre-round + k-group permute (for A inputs) ----------------
__global__ __launch_bounds__(256) void round_permute_kernel(const float4* __restrict__ src,
                                                            float4* __restrict__ dst, int n8) {
  int i = blockIdx.x * blockDim.x + threadIdx.x;
  if (i < n8) {
    float4 v0 = src[2*i];
    float4 v1 = src[2*i + 1];
    float4 w0, w1;
    w0.x = __uint_as_float(f2tf32(v0.x));
    w0.y = __uint_as_float(f2tf32(v1.x));
    w0.z = __uint_as_float(f2tf32(v0.y));
    w0.w = __uint_as_float(f2tf32(v1.y));
    w1.x = __uint_as_float(f2tf32(v0.z));
    w1.y = __uint_as_float(f2tf32(v1.z));
    w1.z = __uint_as_float(f2tf32(v0.w));
    w1.w = __uint_as_float(f2tf32(v1.w));
    dst[2*i] = w0;
    dst[2*i + 1] = w1;
  }
}

// ---------------- transpose + round + k-permute (for B weights) ------------
__global__ __launch_bounds__(256) void transpose_rp_kernel(const float* __restrict__ src,
                                                           float* __restrict__ dst, int ND) {
  __shared__ float t[32][33];
  const int KD = 1024;
  int n0 = blockIdx.x * 32, k0 = blockIdx.y * 32;
  int tx = threadIdx.x & 31, ty8 = threadIdx.x >> 5;
#pragma unroll
  for (int r = 0; r < 4; r++) {
    int k = k0 + ty8 + r*8;
    t[ty8 + r*8][tx] = __uint_as_float(f2tf32(src[(size_t)k*ND + n0 + tx]));
  }
  __syncthreads();
#pragma unroll
  for (int r = 0; r < 4; r++) {
    int n = n0 + ty8 + r*8;
    int c = tx & 7;
    int kpos = (tx & ~7) + 2*(c & 3) + (c >> 2);
    dst[(size_t)n*KD + k0 + kpos] = t[tx][ty8 + r*8];
  }
}

// ---------------- GEMM (R12 proven: 128x128, 4 warps 64x64, single-sync) ---
#define TSTR 40
#define T_BUF (128*TSTR)
#define GEMM_SMEM (4*T_BUF*4)

template <int N, int MODE>
__global__ __launch_bounds__(128, 2) void gemm_tf32(float* __restrict__ Cout) {
  extern __shared__ float sm[];
  float* As[2] = { sm,           sm + T_BUF };
  float* Bs[2] = { sm + 2*T_BUF, sm + 3*T_BUF };

  const float* A  = (MODE == 1) ? (const float*)g_X   : (const float*)g_Y;
  const float* Bt = (MODE == 1) ? (const float*)g_WaT : (const float*)g_WpT;

  const int K = 1024;
  const int tid = threadIdx.x;
  const int warp = tid >> 5, lane = tid & 31;
  const int wm = warp >> 1, wn = warp & 1;
  const int g = lane >> 2, tg = lane & 3;

  const float* Ap = A  + (size_t)(blockIdx.y * 128) * K;
  const float* Bp = Bt + (size_t)(blockIdx.x * 128) * K;

  float acc[4][8][4];
#pragma unroll
  for (int i = 0; i < 4; i++)
#pragma unroll
    for (int j = 0; j < 8; j++)
#pragma unroll
      for (int r = 0; r < 4; r++) acc[i][j][r] = 0.f;

  const int cr = tid >> 3;
  const int cs = (tid & 7) * 4;

  auto load_tile = [&](int kt, int buf) {
    const int k0 = kt * 32;
#pragma unroll
    for (int i = 0; i < 8; i++) {
      int row = cr + i * 16;
      cp_async16(As[buf] + row*TSTR + cs, Ap + (size_t)row * K + k0 + cs);
      cp_async16(Bs[buf] + row*TSTR + cs, Bp + (size_t)row * K + k0 + cs);
    }
    CP_COMMIT();
  };

  load_tile(0, 0);
  const int NT = K / 32;
  for (int kt = 0; kt < NT; kt++) {
    CP_WAIT(0);
    __syncthreads();
    if (kt + 1 < NT) load_tile(kt + 1, (kt + 1) & 1);
    const float* Ab = As[kt & 1];
    const float* Bb = Bs[kt & 1];
#pragma unroll
    for (int ks = 0; ks < 4; ks++) {
      const int kp = ks * 8 + 2 * tg;
      uint32_t bf[8][2];
#pragma unroll
      for (int nt = 0; nt < 8; nt++) {
        int nb = wn * 64 + nt * 8 + g;
        float2 b2 = *(const float2*)&Bb[nb * TSTR + kp];
        bf[nt][0] = __float_as_uint(b2.x);
        bf[nt][1] = __float_as_uint(b2.y);
      }
#pragma unroll
      for (int mt = 0; mt < 4; mt++) {
        int rm = wm * 64 + mt * 16;
        float2 alo = *(const float2*)&Ab[(rm + g    ) * TSTR + kp];
        float2 ahi = *(const float2*)&Ab[(rm + g + 8) * TSTR + kp];
        uint32_t a0 = __float_as_uint(alo.x);
        uint32_t a1 = __float_as_uint(ahi.x);
        uint32_t a2 = __float_as_uint(alo.y);
        uint32_t a3 = __float_as_uint(ahi.y);
#pragma unroll
        for (int nt = 0; nt < 8; nt++)
          mma_tf32(acc[mt][nt], a0, a1, a2, a3, bf[nt][0], bf[nt][1]);
      }
    }
  }

#pragma unroll
  for (int mt = 0; mt < 4; mt++) {
#pragma unroll
    for (int nt = 0; nt < 8; nt++) {
      int row = blockIdx.y * 128 + wm * 64 + mt * 16 + g;
      int col = blockIdx.x * 128 + wn * 64 + nt * 8 + 2 * tg;
      if (MODE == 0) {
        float* p0 = Cout + (size_t)row * N + col;
        float* p1 = Cout + (size_t)(row + 8) * N + col;
        *(float2*)p0 = make_float2(acc[mt][nt][0], acc[mt][nt][1]);
        *(float2*)p1 = make_float2(acc[mt][nt][2], acc[mt][nt][3]);
      } else {
        int which = col >> 10;
        int h = (col >> 6) & 15, d = col & 63;
        float* dst = (which == 0) ? g_Q : ((which == 1) ? g_K : g_V);
        int b0 = row >> 12, t0 = row & 4095;
        float* p0 = dst + ((size_t)((b0 * NHEAD + h) * TLEN + t0)) * HS + d;
        int rowb = row + 8;
        int b1 = rowb >> 12, t1 = rowb & 4095;
        float* p1 = dst + ((size_t)((b1 * NHEAD + h) * TLEN + t1)) * HS + d;
        *(float2*)p0 = make_float2(acc[mt][nt][0], acc[mt][nt][1]);
        *(float2*)p1 = make_float2(acc[mt][nt][2], acc[mt][nt][3]);
      }
    }
  }
}

// ---------------- 64x64 tile helpers: strided ownership ----------
__device__ __forceinline__ void mm_regs_AB(float acc[4][4], const float* __restrict__ A,
                                           const float* __restrict__ B, int ty, int tx) {
#pragma unroll
  for (int i = 0; i < 4; i++)
#pragma unroll
    for (int j = 0; j < 4; j++) acc[i][j] = 0.f;
  for (int k = 0; k < 64; k++) {
    float a0 = A[(ty   )*SSTR+k], a1 = A[(ty+16)*SSTR+k];
    float a2 = A[(ty+32)*SSTR+k], a3 = A[(ty+48)*SSTR+k];
    float b0 = B[k*SSTR+tx   ], b1 = B[k*SSTR+tx+16];
    float b2 = B[k*SSTR+tx+32], b3 = B[k*SSTR+tx+48];
    acc[0][0]=fmaf(a0,b0,acc[0][0]); acc[0][1]=fmaf(a0,b1,acc[0][1]);
    acc[0][2]=fmaf(a0,b2,acc[0][2]); acc[0][3]=fmaf(a0,b3,acc[0][3]);
    acc[1][0]=fmaf(a1,b0,acc[1][0]); acc[1][1]=fmaf(a1,b1,acc[1][1]);
    acc[1][2]=fmaf(a1,b2,acc[1][2]); acc[1][3]=fmaf(a1,b3,acc[1][3]);
    acc[2][0]=fmaf(a2,b0,acc[2][0]); acc[2][1]=fmaf(a2,b1,acc[2][1]);
    acc[2][2]=fmaf(a2,b2,acc[2][2]); acc[2][3]=fmaf(a2,b3,acc[2][3]);
    acc[3][0]=fmaf(a3,b0,acc[3][0]); acc[3][1]=fmaf(a3,b1,acc[3][1]);
    acc[3][2]=fmaf(a3,b2,acc[3][2]); acc[3][3]=fmaf(a3,b3,acc[3][3]);
  }
}
__device__ __forceinline__ void mm_acc_AB(float acc[4][4], const float* __restrict__ A,
                                          const float* __restrict__ B, int ty, int tx) {
  for (int k = 0; k < 64; k++) {
    float a0 = A[(ty   )*SSTR+k], a1 = A[(ty+16)*SSTR+k];
    float a2 = A[(ty+32)*SSTR+k], a3 = A[(ty+48)*SSTR+k];
    float b0 = B[k*SSTR+tx   ], b1 = B[k*SSTR+tx+16];
    float b2 = B[k*SSTR+tx+32], b3 = B[k*SSTR+tx+48];
    acc[0][0]=fmaf(a0,b0,acc[0][0]); acc[0][1]=fmaf(a0,b1,acc[0][1]);
    acc[0][2]=fmaf(a0,b2,acc[0][2]); acc[0][3]=fmaf(a0,b3,acc[0][3]);
    acc[1][0]=fmaf(a1,b0,acc[1][0]); acc[1][1]=fmaf(a1,b1,acc[1][1]);
    acc[1][2]=fmaf(a1,b2,acc[1][2]); acc[1][3]=fmaf(a1,b3,acc[1][3]);
    acc[2][0]=fmaf(a2,b0,acc[2][0]); acc[2][1]=fmaf(a2,b1,acc[2][1]);
    acc[2][2]=fmaf(a2,b2,acc[2][2]); acc[2][3]=fmaf(a2,b3,acc[2][3]);
    acc[3][0]=fmaf(a3,b0,acc[3][0]); acc[3][1]=fmaf(a3,b1,acc[3][1]);
    acc[3][2]=fmaf(a3,b2,acc[3][2]); acc[3][3]=fmaf(a3,b3,acc[3][3]);
  }
}
__device__ __forceinline__ void mm_regs_ABt(float acc[4][4], const float* __restrict__ A,
                                            const float* __restrict__ B, int ty, int tx) {
#pragma unroll
  for (int i = 0; i < 4; i++)
#pragma unroll
    for (int j = 0; j < 4; j++) acc[i][j] = 0.f;
  for (int d = 0; d < 64; d++) {
    float a0 = A[(ty   )*SSTR+d], a1 = A[(ty+16)*SSTR+d];
    float a2 = A[(ty+32)*SSTR+d], a3 = A[(ty+48)*SSTR+d];
    float b0 = B[(tx   )*SSTR+d], b1 = B[(tx+16)*SSTR+d];
    float b2 = B[(tx+32)*SSTR+d], b3 = B[(tx+48)*SSTR+d];
    acc[0][0]=fmaf(a0,b0,acc[0][0]); acc[0][1]=fmaf(a0,b1,acc[0][1]);
    acc[0][2]=fmaf(a0,b2,acc[0][2]); acc[0][3]=fmaf(a0,b3,acc[0][3]);
    acc[1][0]=fmaf(a1,b0,acc[1][0]); acc[1][1]=fmaf(a1,b1,acc[1][1]);
    acc[1][2]=fmaf(a1,b2,acc[1][2]); acc[1][3]=fmaf(a1,b3,acc[1][3]);
    acc[2][0]=fmaf(a2,b0,acc[2][0]); acc[2][1]=fmaf(a2,b1,acc[2][1]);
    acc[2][2]=fmaf(a2,b2,acc[2][2]); acc[2][3]=fmaf(a2,b3,acc[2][3]);
    acc[3][0]=fmaf(a3,b0,acc[3][0]); acc[3][1]=fmaf(a3,b1,acc[3][1]);
    acc[3][2]=fmaf(a3,b2,acc[3][2]); acc[3][3]=fmaf(a3,b3,acc[3][3]);
  }
}
__device__ __forceinline__ void mm_store_AB(float* __restrict__ C, const float* __restrict__ A,
                                            const float* __restrict__ B, int ty, int tx) {
  float acc[4][4];
  mm_regs_AB(acc, A, B, ty, tx);
#pragma unroll
  for (int i = 0; i < 4; i++)
#pragma unroll
    for (int j = 0; j < 4; j++) C[(ty+16*i)*SSTR + tx + 16*j] = acc[i][j];
}
__device__ __forceinline__ float rowmax16(float v) {
#pragma unroll
  for (int off = 8; off; off >>= 1)
    v = fmaxf(v, __shfl_xor_sync(0xffffffffu, v, off, 16));
  return v;
}
__device__ __forceinline__ float rowsum16(float v) {
#pragma unroll
  for (int off = 8; off; off >>= 1)
    v += __shfl_xor_sync(0xffffffffu, v, off, 16);
  return v;
}

// ---------------- Landmarks ----------------
__global__ void landmarks_kernel() {
  const int bh = blockIdx.y, l = blockIdx.x, d = threadIdx.x;
  const float* qb = g_Q + (size_t)bh * HEAD_ELEMS + (size_t)l * 64 * HS;
  const float* kb = g_K + (size_t)bh * HEAD_ELEMS + (size_t)l * 64 * HS;
  float sq = 0.f, sk = 0.f;
  for (int tt = 0; tt < 64; tt++) { sq += qb[tt*HS + d]; sk += kb[tt*HS + d]; }
  g_ql[bh*NLM*HS + l*HS + d] = sq * (1.f/64.f);
  g_kl[bh*NLM*HS + l*HS + d] = sk * (1.f/64.f);
}

// ---------------- Newton-Schulz ----------------
__global__ __launch_bounds__(256) void ns_kernel() {
  extern __shared__ float sm[];
  float* sK  = sm;
  float* sV  = sm + 4160;
  float* sKV = sm + 2*4160;
  float* sT  = sm + 3*4160;
  float* sU  = sm + 4*4160;
  __shared__ float scol[64];
  __shared__ float sden;
  const int bh = blockIdx.x;
  const int tid = threadIdx.x;
  const int ty = tid >> 4, tx = tid & 15;

  for (int e = tid; e < 4096; e += 256) {
    int l = e >> 6, d = e & 63;
    sT[l*SSTR + d] = g_ql[bh*4096 + e];
    sU[l*SSTR + d] = g_kl[bh*4096 + e];
  }
  __syncthreads();
  {
    float acc[4][4];
    mm_regs_ABt(acc, sT, sU, ty, tx);
#pragma unroll
    for (int i = 0; i < 4; i++)
#pragma unroll
      for (int j = 0; j < 4; j++) sK[(ty+16*i)*SSTR + tx + 16*j] = acc[i][j];
  }
  __syncthreads();
  if (tid < 64) {
    float m = -1e30f;
    for (int j = 0; j < 64; j++) m = fmaxf(m, sK[tid*SSTR + j]);
    float s = 0.f;
    for (int j = 0; j < 64; j++) { float e_ = expf(sK[tid*SSTR + j] - m); sK[tid*SSTR + j] = e_; s += e_; }
    float inv = 1.f / s;
    for (int j = 0; j < 64; j++) sK[tid*SSTR + j] *= inv;
  }
  __syncthreads();
  if (tid < 64) {
    float cs = 0.f;
    for (int i = 0; i < 64; i++) cs += sK[i*SSTR + tid];
    scol[tid] = cs;
  }
  __syncthreads();
  if (tid == 0) {
    float mx = scol[0];
    for (int j = 1; j < 64; j++) mx = fmaxf(mx, scol[j]);
    sden = mx;
  }
  __syncthreads();
  const float invden = 1.f / sden;
  for (int e = tid; e < 4096; e += 256) {
    int i = e >> 6, j = e & 63;
    sV[i*SSTR + j] = sK[j*SSTR + i] * invden;
  }
  __syncthreads();
  for (int it = 0; it < 6; it++) {
    mm_store_AB(sKV, sK, sV, ty, tx); __syncthreads();
    for (int e = tid; e < 4096; e += 256) {
      int i = e >> 6, j = e & 63;
      sT[i*SSTR + j] = ((i == j) ? 7.f : 0.f) - sKV[i*SSTR + j];
    }
    __syncthreads();
    mm_store_AB(sU, sKV, sT, ty, tx); __syncthreads();
    for (int e = tid; e < 4096; e += 256) {
      int i = e >> 6, j = e & 63;
      sT[i*SSTR + j] = ((i == j) ? 15.f : 0.f) - sU[i*SSTR + j];
    }
    __syncthreads();
    mm_store_AB(sU, sKV, sT, ty, tx); __syncthreads();
    for (int e = tid; e < 4096; e += 256) {
      int i = e >> 6, j = e & 63;
      sT[i*SSTR + j] = ((i == j) ? 13.f : 0.f) - sU[i*SSTR + j];
    }
    __syncthreads();
    mm_store_AB(sU, sV, sT, ty, tx); __syncthreads();
    for (int e = tid; e < 4096; e += 256) {
      int i = e >> 6, j = e & 63;
      sV[i*SSTR + j] = 0.25f * sU[i*SSTR + j];
    }
    __syncthreads();
  }
  for (int e = tid; e < 4096; e += 256) {
    int l = e >> 6, d = e & 63;
    g_P[bh*4096 + e] = sV[l*SSTR + d];
  }
}

// ---------------- NV partial (R12 proven) ----------------
__global__ __launch_bounds__(256) void nv_partial() {
  extern __shared__ float sm[];
  float* sql = sm;
  float* skP = sm + 4160;
  float* sv  = sm + 2*4160;
  const int bh = blockIdx.y, ts = blockIdx.x;
  const int tid = threadIdx.x, ty = tid >> 4, tx = tid & 15;
  const float* Kb = g_K + (size_t)bh * HEAD_ELEMS;
  const float* Vb = g_V + (size_t)bh * HEAD_ELEMS;

  for (int e = tid; e < 4096; e += 256)
    sql[(e >> 6)*SSTR + (e & 63)] = g_ql[bh*4096 + e];

  float rowm[4], rsum[4], acc[4][4];
#pragma unroll
  for (int i = 0; i < 4; i++) {
    rowm[i] = -1e30f; rsum[i] = 0.f;
#pragma unroll
    for (int j = 0; j < 4; j++) acc[i][j] = 0.f;
  }
  __syncthreads();
  const int tbase = ts * 512;
  for (int c = 0; c < 8; c++) {
    const int t0 = tbase + c * 64;
    for (int e = tid; e < 4096; e += 256) {
      skP[(e >> 6)*SSTR + (e & 63)] = Kb[(size_t)t0 * 64 + e];
      sv [(e >> 6)*SSTR + (e & 63)] = Vb[(size_t)t0 * 64 + e];
    }
    __syncthreads();
    float s[4][4];
    mm_regs_ABt(s, sql, skP, ty, tx);
#pragma unroll
    for (int i = 0; i < 4; i++) {
      float mx = fmaxf(fmaxf(s[i][0], s[i][1]), fmaxf(s[i][2], s[i][3]));
      mx = rowmax16(mx);
      float nm = fmaxf(rowm[i], mx);
      float al = expf(rowm[i] - nm);
      rowm[i] = nm;
#pragma unroll
      for (int j = 0; j < 4; j++) s[i][j] = expf(s[i][j] - nm);
      float ls = s[i][0] + s[i][1] + s[i][2] + s[i][3];
      ls = rowsum16(ls);
      rsum[i] = rsum[i] * al + ls;
#pragma unroll
      for (int j = 0; j < 4; j++) acc[i][j] *= al;
    }
    __syncthreads();
#pragma unroll
    for (int i = 0; i < 4; i++)
#pragma unroll
      for (int j = 0; j < 4; j++) skP[(ty+16*i)*SSTR + tx + 16*j] = s[i][j];
    __syncthreads();
    mm_acc_AB(acc, skP, sv, ty, tx);
    __syncthreads();
  }
  const size_t pb = (size_t)(bh*8 + ts) * 4096;
#pragma unroll
  for (int i = 0; i < 4; i++)
#pragma unroll
    for (int j = 0; j < 4; j++)
      g_NVp[pb + (ty+16*i)*64 + tx + 16*j] = acc[i][j];
  if (tx == 0) {
#pragma unroll
    for (int i = 0; i < 4; i++) {
      g_mp[(bh*8 + ts)*64 + ty + 16*i] = rowm[i];
      g_sp[(bh*8 + ts)*64 + ty + 16*i] = rsum[i];
    }
  }
}

// ---------------- FUSED combine + Z: NV built in smem, Z = P @ NV ----------
__global__ __launch_bounds__(256) void combine_z_kernel() {
  __shared__ float sA[64*SSTR];     // P
  __shared__ float sB[64*SSTR];     // NV
  __shared__ float W[8][64];
  __shared__ float D[64];
  const int bh = blockIdx.x, tid = threadIdx.x;
  const int ty = tid >> 4, tx = tid & 15;

  if (tid < 64) {
    float mp[8];
    float m = -1e30f;
    for (int p = 0; p < 8; p++) { mp[p] = g_mp[(bh*8 + p)*64 + tid]; m = fmaxf(m, mp[p]); }
    float dd = 0.f;
    for (int p = 0; p < 8; p++) {
      float w = expf(mp[p] - m);
      W[p][tid] = w;
      dd += g_sp[(bh*8 + p)*64 + tid] * w;
    }
    D[tid] = dd;
  }
  for (int e = tid; e < 4096; e += 256) {
    int l = e >> 6, d = e & 63;
    sA[l*SSTR + d] = g_P[bh*4096 + e];
  }
  __syncthreads();
  for (int e = tid; e < 4096; e += 256) {
    int l = e >> 6, d = e & 63;
    float v = 0.f;
    for (int p = 0; p < 8; p++)
      v += g_NVp[(size_t)(bh*8 + p)*4096 + e] * W[p][l];
    sB[l*SSTR + d] = v / D[l];
  }
  __syncthreads();
  float acc[4][4];
  mm_regs_AB(acc, sA, sB, ty, tx);
#pragma unroll
  for (int i = 0; i < 4; i++)
#pragma unroll
    for (int j = 0; j < 4; j++)
      g_Z[bh*4096 + (ty+16*i)*64 + tx + 16*j] = acc[i][j];
}

// ---------------- Y = softmax(q @ k_l^T) @ Z, rounded + k-permuted ---------
__global__ __launch_bounds__(256) void ly_kernel() {
  extern __shared__ float sm[];
  float* sqP = sm;
  float* skl = sm + 4160;
  float* sZ  = sm + 2*4160;
  const int bh = blockIdx.y, tt = blockIdx.x;
  const int tid = threadIdx.x, ty = tid >> 4, tx = tid & 15;
  const int t0 = tt * 64;
  const float* Qb = g_Q + (size_t)bh * HEAD_ELEMS + (size_t)t0 * 64;
  for (int e = tid; e < 4096; e += 256) {
    int l = e >> 6, d = e & 63;
    sqP[l*SSTR + d] = Qb[e];
    skl[l*SSTR + d] = g_kl[bh*4096 + e];
    sZ [l*SSTR + d] = g_Z [bh*4096 + e];
  }
  __syncthreads();
  float s[4][4];
  mm_regs_ABt(s, sqP, skl, ty, tx);
  float rs[4];
#pragma unroll
  for (int i = 0; i < 4; i++) {
    float mx = fmaxf(fmaxf(s[i][0], s[i][1]), fmaxf(s[i][2], s[i][3]));
    mx = rowmax16(mx);
#pragma unroll
    for (int j = 0; j < 4; j++) s[i][j] = expf(s[i][j] - mx);
    float ls = s[i][0] + s[i][1] + s[i][2] + s[i][3];
    rs[i] = rowsum16(ls);
  }
  __syncthreads();
#pragma unroll
  for (int i = 0; i < 4; i++)
#pragma unroll
    for (int j = 0; j < 4; j++) sqP[(ty+16*i)*SSTR + tx + 16*j] = s[i][j];
  __syncthreads();
  float acc[4][4];
  mm_regs_AB(acc, sqP, sZ, ty, tx);
  const int b = bh >> 4, h = bh & 15;
  const int w = tx & 7;
  const int cbase = h*HS + (tx & ~7) + 2*(w & 3) + (w >> 2);
#pragma unroll
  for (int i = 0; i < 4; i++) {
    float inv = 1.f / rs[i];
    float* prow = g_Y + (size_t)(b*TLEN + t0 + ty + 16*i) * CDIM;
#pragma unroll
    for (int j = 0; j < 4; j++) {
      float v = __uint_as_float(f2tf32(acc[i][j] * inv));
      prow[cbase + 16*j] = v;
    }
  }
}

// ---------------- Launch ----------------
extern "C" void kernel_launch(void* const* d_in, const int* in_sizes, int n_in,
                              void* d_out, int out_size) {
  const float* x  = (const float*)d_in[0];
  const float* Wa = (const float*)d_in[1];
  const float* Wp = (const float*)d_in[2];
  float* out = (float*)d_out;

  const int smem5 = 5 * 4160 * 4;
  const int smem3 = 3 * 4160 * 4;
  cudaFuncSetAttribute(ns_kernel,  cudaFuncAttributeMaxDynamicSharedMemorySize, smem5);
  cudaFuncSetAttribute(nv_partial, cudaFuncAttributeMaxDynamicSharedMemorySize, smem3);
  cudaFuncSetAttribute(ly_kernel,  cudaFuncAttributeMaxDynamicSharedMemorySize, smem3);
  cudaFuncSetAttribute((const void*)gemm_tf32<3072,1>, cudaFuncAttributeMaxDynamicSharedMemorySize, GEMM_SMEM);
  cudaFuncSetAttribute((const void*)gemm_tf32<1024,0>, cudaFuncAttributeMaxDynamicSharedMemorySize, GEMM_SMEM);

  float* dX;  cudaGetSymbolAddress((void**)&dX,  g_X);
  float* dWaT; cudaGetSymbolAddress((void**)&dWaT, g_WaT);
  float* dWpT; cudaGetSymbolAddress((void**)&dWpT, g_WpT);
  round_permute_kernel<<<(BATCH*TLEN*CDIM/8 + 255)/256, 256>>>((const float4*)x, (float4*)dX, BATCH*TLEN*CDIM/8);
  transpose_rp_kernel<<<dim3(3*CDIM/32, CDIM/32), 256>>>(Wa, dWaT, 3*CDIM);
  transpose_rp_kernel<<<dim3(CDIM/32, CDIM/32), 256>>>(Wp, dWpT, CDIM);

  gemm_tf32<3072,1><<<dim3(24, 128), 128, GEMM_SMEM>>>(nullptr);
  landmarks_kernel<<<dim3(NLM, BH), 64>>>();
  ns_kernel<<<BH, 256, smem5>>>();
  nv_partial<<<dim3(8, BH), 256, smem3>>>();
  combine_z_kernel<<<BH, 256>>>();
  ly_kernel<<<dim3(64, BH), 256, smem3>>>();
  gemm_tf32<1024,0><<<dim3(8, 128), 128, GEMM_SMEM>>>(out);
}

// round 15
// speedup vs baseline: 1.1195x; 1.0036x over previous
#include <cuda_runtime.h>
#include <math.h>
#include <stdint.h>

// ---------------- Problem constants ----------------
#define NHEAD 16
#define HS    64
#define NLM   64
#define TLEN  4096
#define BATCH 4
#define BH    64
#define CDIM  1024
#define HEAD_ELEMS (TLEN*HS)
#define QKV_ELEMS  (BH*HEAD_ELEMS)
#define SSTR  65

// ---------------- Scratch ----------------
__device__ float g_Q[QKV_ELEMS];
__device__ float g_K[QKV_ELEMS];
__device__ float g_V[QKV_ELEMS];
__device__ float g_ql[BH*NLM*HS];
__device__ float g_kl[BH*NLM*HS];
__device__ float g_NVp[BH*8*NLM*HS];
__device__ float g_mp [BH*8*NLM];
__device__ float g_sp [BH*8*NLM];
__device__ float g_Z  [BH*NLM*HS];
__device__ float g_Y  [BATCH*TLEN*CDIM];   // tf32-rounded, k-permuted (GEMM2 A)
__device__ float g_X  [BATCH*TLEN*CDIM];   // tf32-rounded, k-permuted (GEMM1 A)
__device__ float g_WaT[3*CDIM*CDIM];       // W_attn^T [n][k], tf32-rounded, k-permuted
__device__ float g_WpT[CDIM*CDIM];         // W_proj^T [n][k], tf32-rounded, k-permuted

// ======================= tf32 helpers ======================================
__device__ __forceinline__ uint32_t f2tf32(float x) {
  uint32_t u;
  asm("cvt.rna.tf32.f32 %0, %1;" : "=r"(u) : "f"(x));
  return u;
}
__device__ __forceinline__ void mma_tf32(float c[4], uint32_t a0, uint32_t a1,
                                         uint32_t a2, uint32_t a3,
                                         uint32_t b0, uint32_t b1) {
  asm volatile(
    "mma.sync.aligned.m16n8k8.row.col.f32.tf32.tf32.f32 "
    "{%0,%1,%2,%3}, {%4,%5,%6,%7}, {%8,%9}, {%0,%1,%2,%3};"
    : "+f"(c[0]), "+f"(c[1]), "+f"(c[2]), "+f"(c[3])
    : "r"(a0), "r"(a1), "r"(a2), "r"(a3), "r"(b0), "r"(b1));
}
__device__ __forceinline__ void cp_async16(void* smem_dst, const void* gsrc) {
  uint32_t s = (uint32_t)__cvta_generic_to_shared(smem_dst);
  asm volatile("cp.async.ca.shared.global [%0], [%1], 16;\n" :: "r"(s), "l"(gsrc));
}
#define CP_COMMIT() asm volatile("cp.async.commit_group;\n" ::: "memory")
#define CP_WAIT(n)  asm volatile("cp.async.wait_group %0;\n" :: "n"(n) : "memory")

// ---------------- pre-round + k-group permute (for A inputs) ----------------
__global__ __launch_bounds__(256) void round_permute_kernel(const float4* __restrict__ src,
                                                            float4* __restrict__ dst, int n8) {
  int i = blockIdx.x * blockDim.x + threadIdx.x;
  if (i < n8) {
    float4 v0 = src[2*i];
    float4 v1 = src[2*i + 1];
    float4 w0, w1;
    w0.x = __uint_as_float(f2tf32(v0.x));
    w0.y = __uint_as_float(f2tf32(v1.x));
    w0.z = __uint_as_float(f2tf32(v0.y));
    w0.w = __uint_as_float(f2tf32(v1.y));
    w1.x = __uint_as_float(f2tf32(v0.z));
    w1.y = __uint_as_float(f2tf32(v1.z));
    w1.z = __uint_as_float(f2tf32(v0.w));
    w1.w = __uint_as_float(f2tf32(v1.w));
    dst[2*i] = w0;
    dst[2*i + 1] = w1;
  }
}

// ---------------- transpose + round + k-permute (for B weights) ------------
__global__ __launch_bounds__(256) void transpose_rp_kernel(const float* __restrict__ src,
                                                           float* __restrict__ dst, int ND) {
  __shared__ float t[32][33];
  const int KD = 1024;
  int n0 = blockIdx.x * 32, k0 = blockIdx.y * 32;
  int tx = threadIdx.x & 31, ty8 = threadIdx.x >> 5;
#pragma unroll
  for (int r = 0; r < 4; r++) {
    int k = k0 + ty8 + r*8;
    t[ty8 + r*8][tx] = __uint_as_float(f2tf32(src[(size_t)k*ND + n0 + tx]));
  }
  __syncthreads();
#pragma unroll
  for (int r = 0; r < 4; r++) {
    int n = n0 + ty8 + r*8;
    int c = tx & 7;
    int kpos = (tx & ~7) + 2*(c & 3) + (c >> 2);
    dst[(size_t)n*KD + k0 + kpos] = t[tx][ty8 + r*8];
  }
}

// ---------------- GEMM (R12 proven: 128x128, 4 warps 64x64, single-sync) ---
#define TSTR 40
#define T_BUF (128*TSTR)
#define GEMM_SMEM (4*T_BUF*4)

template <int N, int MODE>
__global__ __launch_bounds__(128, 2) void gemm_tf32(float* __restrict__ Cout) {
  extern __shared__ float sm[];
  float* As[2] = { sm,           sm + T_BUF };
  float* Bs[2] = { sm + 2*T_BUF, sm + 3*T_BUF };

  const float* A  = (MODE == 1) ? (const float*)g_X   : (const float*)g_Y;
  const float* Bt = (MODE == 1) ? (const float*)g_WaT : (const float*)g_WpT;

  const int K = 1024;
  const int tid = threadIdx.x;
  const int warp = tid >> 5, lane = tid & 31;
  const int wm = warp >> 1, wn = warp & 1;
  const int g = lane >> 2, tg = lane & 3;

  const float* Ap = A  + (size_t)(blockIdx.y * 128) * K;
  const float* Bp = Bt + (size_t)(blockIdx.x * 128) * K;

  float acc[4][8][4];
#pragma unroll
  for (int i = 0; i < 4; i++)
#pragma unroll
    for (int j = 0; j < 8; j++)
#pragma unroll
      for (int r = 0; r < 4; r++) acc[i][j][r] = 0.f;

  const int cr = tid >> 3;
  const int cs = (tid & 7) * 4;

  auto load_tile = [&](int kt, int buf) {
    const int k0 = kt * 32;
#pragma unroll
    for (int i = 0; i < 8; i++) {
      int row = cr + i * 16;
      cp_async16(As[buf] + row*TSTR + cs, Ap + (size_t)row * K + k0 + cs);
      cp_async16(Bs[buf] + row*TSTR + cs, Bp + (size_t)row * K + k0 + cs);
    }
    CP_COMMIT();
  };

  load_tile(0, 0);
  const int NT = K / 32;
  for (int kt = 0; kt < NT; kt++) {
    CP_WAIT(0);
    __syncthreads();
    if (kt + 1 < NT) load_tile(kt + 1, (kt + 1) & 1);
    const float* Ab = As[kt & 1];
    const float* Bb = Bs[kt & 1];
#pragma unroll
    for (int ks = 0; ks < 4; ks++) {
      const int kp = ks * 8 + 2 * tg;
      uint32_t bf[8][2];
#pragma unroll
      for (int nt = 0; nt < 8; nt++) {
        int nb = wn * 64 + nt * 8 + g;
        float2 b2 = *(const float2*)&Bb[nb * TSTR + kp];
        bf[nt][0] = __float_as_uint(b2.x);
        bf[nt][1] = __float_as_uint(b2.y);
      }
#pragma unroll
      for (int mt = 0; mt < 4; mt++) {
        int rm = wm * 64 + mt * 16;
        float2 alo = *(const float2*)&Ab[(rm + g    ) * TSTR + kp];
        float2 ahi = *(const float2*)&Ab[(rm + g + 8) * TSTR + kp];
        uint32_t a0 = __float_as_uint(alo.x);
        uint32_t a1 = __float_as_uint(ahi.x);
        uint32_t a2 = __float_as_uint(alo.y);
        uint32_t a3 = __float_as_uint(ahi.y);
#pragma unroll
        for (int nt = 0; nt < 8; nt++)
          mma_tf32(acc[mt][nt], a0, a1, a2, a3, bf[nt][0], bf[nt][1]);
      }
    }
  }

#pragma unroll
  for (int mt = 0; mt < 4; mt++) {
#pragma unroll
    for (int nt = 0; nt < 8; nt++) {
      int row = blockIdx.y * 128 + wm * 64 + mt * 16 + g;
      int col = blockIdx.x * 128 + wn * 64 + nt * 8 + 2 * tg;
      if (MODE == 0) {
        float* p0 = Cout + (size_t)row * N + col;
        float* p1 = Cout + (size_t)(row + 8) * N + col;
        *(float2*)p0 = make_float2(acc[mt][nt][0], acc[mt][nt][1]);
        *(float2*)p1 = make_float2(acc[mt][nt][2], acc[mt][nt][3]);
      } else {
        int which = col >> 10;
        int h = (col >> 6) & 15, d = col & 63;
        float* dst = (which == 0) ? g_Q : ((which == 1) ? g_K : g_V);
        int b0 = row >> 12, t0 = row & 4095;
        float* p0 = dst + ((size_t)((b0 * NHEAD + h) * TLEN + t0)) * HS + d;
        int rowb = row + 8;
        int b1 = rowb >> 12, t1 = rowb & 4095;
        float* p1 = dst + ((size_t)((b1 * NHEAD + h) * TLEN + t1)) * HS + d;
        *(float2*)p0 = make_float2(acc[mt][nt][0], acc[mt][nt][1]);
        *(float2*)p1 = make_float2(acc[mt][nt][2], acc[mt][nt][3]);
      }
    }
  }
}

// ---------------- 64x64 tile helpers: strided ownership ----------
__device__ __forceinline__ void mm_regs_AB(float acc[4][4], const float* __restrict__ A,
                                           const float* __restrict__ B, int ty, int tx) {
#pragma unroll
  for (int i = 0; i < 4; i++)
#pragma unroll
    for (int j = 0; j < 4; j++) acc[i][j] = 0.f;
  for (int k = 0; k < 64; k++) {
    float a0 = A[(ty   )*SSTR+k], a1 = A[(ty+16)*SSTR+k];
    float a2 = A[(ty+32)*SSTR+k], a3 = A[(ty+48)*SSTR+k];
    float b0 = B[k*SSTR+tx   ], b1 = B[k*SSTR+tx+16];
    float b2 = B[k*SSTR+tx+32], b3 = B[k*SSTR+tx+48];
    acc[0][0]=fmaf(a0,b0,acc[0][0]); acc[0][1]=fmaf(a0,b1,acc[0][1]);
    acc[0][2]=fmaf(a0,b2,acc[0][2]); acc[0][3]=fmaf(a0,b3,acc[0][3]);
    acc[1][0]=fmaf(a1,b0,acc[1][0]); acc[1][1]=fmaf(a1,b1,acc[1][1]);
    acc[1][2]=fmaf(a1,b2,acc[1][2]); acc[1][3]=fmaf(a1,b3,acc[1][3]);
    acc[2][0]=fmaf(a2,b0,acc[2][0]); acc[2][1]=fmaf(a2,b1,acc[2][1]);
    acc[2][2]=fmaf(a2,b2,acc[2][2]); acc[2][3]=fmaf(a2,b3,acc[2][3]);
    acc[3][0]=fmaf(a3,b0,acc[3][0]); acc[3][1]=fmaf(a3,b1,acc[3][1]);
    acc[3][2]=fmaf(a3,b2,acc[3][2]); acc[3][3]=fmaf(a3,b3,acc[3][3]);
  }
}
__device__ __forceinline__ void mm_acc_AB(float acc[4][4], const float* __restrict__ A,
                                          const float* __restrict__ B, int ty, int tx) {
  for (int k = 0; k < 64; k++) {
    float a0 = A[(ty   )*SSTR+k], a1 = A[(ty+16)*SSTR+k];
    float a2 = A[(ty+32)*SSTR+k], a3 = A[(ty+48)*SSTR+k];
    float b0 = B[k*SSTR+tx   ], b1 = B[k*SSTR+tx+16];
    float b2 = B[k*SSTR+tx+32], b3 = B[k*SSTR+tx+48];
    acc[0][0]=fmaf(a0,b0,acc[0][0]); acc[0][1]=fmaf(a0,b1,acc[0][1]);
    acc[0][2]=fmaf(a0,b2,acc[0][2]); acc[0][3]=fmaf(a0,b3,acc[0][3]);
    acc[1][0]=fmaf(a1,b0,acc[1][0]); acc[1][1]=fmaf(a1,b1,acc[1][1]);
    acc[1][2]=fmaf(a1,b2,acc[1][2]); acc[1][3]=fmaf(a1,b3,acc[1][3]);
    acc[2][0]=fmaf(a2,b0,acc[2][0]); acc[2][1]=fmaf(a2,b1,acc[2][1]);
    acc[2][2]=fmaf(a2,b2,acc[2][2]); acc[2][3]=fmaf(a2,b3,acc[2][3]);
    acc[3][0]=fmaf(a3,b0,acc[3][0]); acc[3][1]=fmaf(a3,b1,acc[3][1]);
    acc[3][2]=fmaf(a3,b2,acc[3][2]); acc[3][3]=fmaf(a3,b3,acc[3][3]);
  }
}
__device__ __forceinline__ void mm_regs_ABt(float acc[4][4], const float* __restrict__ A,
                                            const float* __restrict__ B, int ty, int tx) {
#pragma unroll
  for (int i = 0; i < 4; i++)
#pragma unroll
    for (int j = 0; j < 4; j++) acc[i][j] = 0.f;
  for (int d = 0; d < 64; d++) {
    float a0 = A[(ty   )*SSTR+d], a1 = A[(ty+16)*SSTR+d];
    float a2 = A[(ty+32)*SSTR+d], a3 = A[(ty+48)*SSTR+d];
    float b0 = B[(tx   )*SSTR+d], b1 = B[(tx+16)*SSTR+d];
    float b2 = B[(tx+32)*SSTR+d], b3 = B[(tx+48)*SSTR+d];
    acc[0][0]=fmaf(a0,b0,acc[0][0]); acc[0][1]=fmaf(a0,b1,acc[0][1]);
    acc[0][2]=fmaf(a0,b2,acc[0][2]); acc[0][3]=fmaf(a0,b3,acc[0][3]);
    acc[1][0]=fmaf(a1,b0,acc[1][0]); acc[1][1]=fmaf(a1,b1,acc[1][1]);
    acc[1][2]=fmaf(a1,b2,acc[1][2]); acc[1][3]=fmaf(a1,b3,acc[1][3]);
    acc[2][0]=fmaf(a2,b0,acc[2][0]); acc[2][1]=fmaf(a2,b1,acc[2][1]);
    acc[2][2]=fmaf(a2,b2,acc[2][2]); acc[2][3]=fmaf(a2,b3,acc[2][3]);
    acc[3][0]=fmaf(a3,b0,acc[3][0]); acc[3][1]=fmaf(a3,b1,acc[3][1]);
    acc[3][2]=fmaf(a3,b2,acc[3][2]); acc[3][3]=fmaf(a3,b3,acc[3][3]);
  }
}
__device__ __forceinline__ void mm_store_AB(float* __restrict__ C, const float* __restrict__ A,
                                            const float* __restrict__ B, int ty, int tx) {
  float acc[4][4];
  mm_regs_AB(acc, A, B, ty, tx);
#pragma unroll
  for (int i = 0; i < 4; i++)
#pragma unroll
    for (int j = 0; j < 4; j++) C[(ty+16*i)*SSTR + tx + 16*j] = acc[i][j];
}
__device__ __forceinline__ float rowmax16(float v) {
#pragma unroll
  for (int off = 8; off; off >>= 1)
    v = fmaxf(v, __shfl_xor_sync(0xffffffffu, v, off, 16));
  return v;
}
__device__ __forceinline__ float rowsum16(float v) {
#pragma unroll
  for (int off = 8; off; off >>= 1)
    v += __shfl_xor_sync(0xffffffffu, v, off, 16);
  return v;
}

// ---------------- Landmarks ----------------
__global__ void landmarks_kernel() {
  const int bh = blockIdx.y, l = blockIdx.x, d = threadIdx.x;
  const float* qb = g_Q + (size_t)bh * HEAD_ELEMS + (size_t)l * 64 * HS;
  const float* kb = g_K + (size_t)bh * HEAD_ELEMS + (size_t)l * 64 * HS;
  float sq = 0.f, sk = 0.f;
  for (int tt = 0; tt < 64; tt++) { sq += qb[tt*HS + d]; sk += kb[tt*HS + d]; }
  g_ql[bh*NLM*HS + l*HS + d] = sq * (1.f/64.f);
  g_kl[bh*NLM*HS + l*HS + d] = sk * (1.f/64.f);
}

// ---------------- NV partial (R12 proven) ----------------
__global__ __launch_bounds__(256) void nv_partial() {
  extern __shared__ float sm[];
  float* sql = sm;
  float* skP = sm + 4160;
  float* sv  = sm + 2*4160;
  const int bh = blockIdx.y, ts = blockIdx.x;
  const int tid = threadIdx.x, ty = tid >> 4, tx = tid & 15;
  const float* Kb = g_K + (size_t)bh * HEAD_ELEMS;
  const float* Vb = g_V + (size_t)bh * HEAD_ELEMS;

  for (int e = tid; e < 4096; e += 256)
    sql[(e >> 6)*SSTR + (e & 63)] = g_ql[bh*4096 + e];

  float rowm[4], rsum[4], acc[4][4];
#pragma unroll
  for (int i = 0; i < 4; i++) {
    rowm[i] = -1e30f; rsum[i] = 0.f;
#pragma unroll
    for (int j = 0; j < 4; j++) acc[i][j] = 0.f;
  }
  __syncthreads();
  const int tbase = ts * 512;
  for (int c = 0; c < 8; c++) {
    const int t0 = tbase + c * 64;
    for (int e = tid; e < 4096; e += 256) {
      skP[(e >> 6)*SSTR + (e & 63)] = Kb[(size_t)t0 * 64 + e];
      sv [(e >> 6)*SSTR + (e & 63)] = Vb[(size_t)t0 * 64 + e];
    }
    __syncthreads();
    float s[4][4];
    mm_regs_ABt(s, sql, skP, ty, tx);
#pragma unroll
    for (int i = 0; i < 4; i++) {
      float mx = fmaxf(fmaxf(s[i][0], s[i][1]), fmaxf(s[i][2], s[i][3]));
      mx = rowmax16(mx);
      float nm = fmaxf(rowm[i], mx);
      float al = expf(rowm[i] - nm);
      rowm[i] = nm;
#pragma unroll
      for (int j = 0; j < 4; j++) s[i][j] = expf(s[i][j] - nm);
      float ls = s[i][0] + s[i][1] + s[i][2] + s[i][3];
      ls = rowsum16(ls);
      rsum[i] = rsum[i] * al + ls;
#pragma unroll
      for (int j = 0; j < 4; j++) acc[i][j] *= al;
    }
    __syncthreads();
#pragma unroll
    for (int i = 0; i < 4; i++)
#pragma unroll
      for (int j = 0; j < 4; j++) skP[(ty+16*i)*SSTR + tx + 16*j] = s[i][j];
    __syncthreads();
    mm_acc_AB(acc, skP, sv, ty, tx);
    __syncthreads();
  }
  const size_t pb = (size_t)(bh*8 + ts) * 4096;
#pragma unroll
  for (int i = 0; i < 4; i++)
#pragma unroll
    for (int j = 0; j < 4; j++)
      g_NVp[pb + (ty+16*i)*64 + tx + 16*j] = acc[i][j];
  if (tx == 0) {
#pragma unroll
    for (int i = 0; i < 4; i++) {
      g_mp[(bh*8 + ts)*64 + ty + 16*i] = rowm[i];
      g_sp[(bh*8 + ts)*64 + ty + 16*i] = rsum[i];
    }
  }
}

// ---------------- FUSED: Newton-Schulz + combine + Z --------------------
// P stays in smem (sV); NV built in sKV; Z = P @ NV written to g_Z.
__global__ __launch_bounds__(256) void ns_combine_z_kernel() {
  extern __shared__ float sm[];
  float* sK  = sm;
  float* sV  = sm + 4160;          // ends as P
  float* sKV = sm + 2*4160;        // reused as NV for combine
  float* sT  = sm + 3*4160;
  float* sU  = sm + 4*4160;
  __shared__ float scol[64];
  __shared__ float sden;
  __shared__ float W[8][64];
  __shared__ float D[64];
  const int bh = blockIdx.x;
  const int tid = threadIdx.x;
  const int ty = tid >> 4, tx = tid & 15;

  // ---- Newton-Schulz (identical to ns_kernel) ----
  for (int e = tid; e < 4096; e += 256) {
    int l = e >> 6, d = e & 63;
    sT[l*SSTR + d] = g_ql[bh*4096 + e];
    sU[l*SSTR + d] = g_kl[bh*4096 + e];
  }
  __syncthreads();
  {
    float acc[4][4];
    mm_regs_ABt(acc, sT, sU, ty, tx);
#pragma unroll
    for (int i = 0; i < 4; i++)
#pragma unroll
      for (int j = 0; j < 4; j++) sK[(ty+16*i)*SSTR + tx + 16*j] = acc[i][j];
  }
  __syncthreads();
  if (tid < 64) {
    float m = -1e30f;
    for (int j = 0; j < 64; j++) m = fmaxf(m, sK[tid*SSTR + j]);
    float s = 0.f;
    for (int j = 0; j < 64; j++) { float e_ = expf(sK[tid*SSTR + j] - m); sK[tid*SSTR + j] = e_; s += e_; }
    float inv = 1.f / s;
    for (int j = 0; j < 64; j++) sK[tid*SSTR + j] *= inv;
  }
  __syncthreads();
  if (tid < 64) {
    float cs = 0.f;
    for (int i = 0; i < 64; i++) cs += sK[i*SSTR + tid];
    scol[tid] = cs;
  }
  __syncthreads();
  if (tid == 0) {
    float mx = scol[0];
    for (int j = 1; j < 64; j++) mx = fmaxf(mx, scol[j]);
    sden = mx;
  }
  __syncthreads();
  const float invden = 1.f / sden;
  for (int e = tid; e < 4096; e += 256) {
    int i = e >> 6, j = e & 63;
    sV[i*SSTR + j] = sK[j*SSTR + i] * invden;
  }
  __syncthreads();
  for (int it = 0; it < 6; it++) {
    mm_store_AB(sKV, sK, sV, ty, tx); __syncthreads();
    for (int e = tid; e < 4096; e += 256) {
      int i = e >> 6, j = e & 63;
      sT[i*SSTR + j] = ((i == j) ? 7.f : 0.f) - sKV[i*SSTR + j];
    }
    __syncthreads();
    mm_store_AB(sU, sKV, sT, ty, tx); __syncthreads();
    for (int e = tid; e < 4096; e += 256) {
      int i = e >> 6, j = e & 63;
      sT[i*SSTR + j] = ((i == j) ? 15.f : 0.f) - sU[i*SSTR + j];
    }
    __syncthreads();
    mm_store_AB(sU, sKV, sT, ty, tx); __syncthreads();
    for (int e = tid; e < 4096; e += 256) {
      int i = e >> 6, j = e & 63;
      sT[i*SSTR + j] = ((i == j) ? 13.f : 0.f) - sU[i*SSTR + j];
    }
    __syncthreads();
    mm_store_AB(sU, sV, sT, ty, tx); __syncthreads();
    for (int e = tid; e < 4096; e += 256) {
      int i = e >> 6, j = e & 63;
      sV[i*SSTR + j] = 0.25f * sU[i*SSTR + j];
    }
    __syncthreads();
  }
  // sV now holds P (same element positions z_kernel used).

  // ---- combine: NV into sKV ----
  if (tid < 64) {
    float mp[8];
    float m = -1e30f;
    for (int p = 0; p < 8; p++) { mp[p] = g_mp[(bh*8 + p)*64 + tid]; m = fmaxf(m, mp[p]); }
    float dd = 0.f;
    for (int p = 0; p < 8; p++) {
      float w = expf(mp[p] - m);
      W[p][tid] = w;
      dd += g_sp[(bh*8 + p)*64 + tid] * w;
    }
    D[tid] = dd;
  }
  __syncthreads();
  for (int e = tid; e < 4096; e += 256) {
    int l = e >> 6, d = e & 63;
    float v = 0.f;
    for (int p = 0; p < 8; p++)
      v += g_NVp[(size_t)(bh*8 + p)*4096 + e] * W[p][l];
    sKV[l*SSTR + d] = v / D[l];
  }
  __syncthreads();

  // ---- Z = P @ NV ----
  float acc[4][4];
  mm_regs_AB(acc, sV, sKV, ty, tx);
#pragma unroll
  for (int i = 0; i < 4; i++)
#pragma unroll
    for (int j = 0; j < 4; j++)
      g_Z[bh*4096 + (ty+16*i)*64 + tx + 16*j] = acc[i][j];
}

// ---------------- Y = softmax(q @ k_l^T) @ Z, rounded + k-permuted ---------
__global__ __launch_bounds__(256) void ly_kernel() {
  extern __shared__ float sm[];
  float* sqP = sm;
  float* skl = sm + 4160;
  float* sZ  = sm + 2*4160;
  const int bh = blockIdx.y, tt = blockIdx.x;
  const int tid = threadIdx.x, ty = tid >> 4, tx = tid & 15;
  const int t0 = tt * 64;
  const float* Qb = g_Q + (size_t)bh * HEAD_ELEMS + (size_t)t0 * 64;
  for (int e = tid; e < 4096; e += 256) {
    int l = e >> 6, d = e & 63;
    sqP[l*SSTR + d] = Qb[e];
    skl[l*SSTR + d] = g_kl[bh*4096 + e];
    sZ [l*SSTR + d] = g_Z [bh*4096 + e];
  }
  __syncthreads();
  float s[4][4];
  mm_regs_ABt(s, sqP, skl, ty, tx);
  float rs[4];
#pragma unroll
  for (int i = 0; i < 4; i++) {
    float mx = fmaxf(fmaxf(s[i][0], s[i][1]), fmaxf(s[i][2], s[i][3]));
    mx = rowmax16(mx);
#pragma unroll
    for (int j = 0; j < 4; j++) s[i][j] = expf(s[i][j] - mx);
    float ls = s[i][0] + s[i][1] + s[i][2] + s[i][3];
    rs[i] = rowsum16(ls);
  }
  __syncthreads();
#pragma unroll
  for (int i = 0; i < 4; i++)
#pragma unroll
    for (int j = 0; j < 4; j++) sqP[(ty+16*i)*SSTR + tx + 16*j] = s[i][j];
  __syncthreads();
  float acc[4][4];
  mm_regs_AB(acc, sqP, sZ, ty, tx);
  const int b = bh >> 4, h = bh & 15;
  const int w = tx & 7;
  const int cbase = h*HS + (tx & ~7) + 2*(w & 3) + (w >> 2);
#pragma unroll
  for (int i = 0; i < 4; i++) {
    float inv = 1.f / rs[i];
    float* prow = g_Y + (size_t)(b*TLEN + t0 + ty + 16*i) * CDIM;
#pragma unroll
    for (int j = 0; j < 4; j++) {
      float v = __uint_as_float(f2tf32(acc[i][j] * inv));
      prow[cbase + 16*j] = v;
    }
  }
}

// ---------------- Launch ----------------
extern "C" void kernel_launch(void* const* d_in, const int* in_sizes, int n_in,
                              void* d_out, int out_size) {
  const float* x  = (const float*)d_in[0];
  const float* Wa = (const float*)d_in[1];
  const float* Wp = (const float*)d_in[2];
  float* out = (float*)d_out;

  const int smem5 = 5 * 4160 * 4;
  const int smem3 = 3 * 4160 * 4;
  cudaFuncSetAttribute(ns_combine_z_kernel, cudaFuncAttributeMaxDynamicSharedMemorySize, smem5);
  cudaFuncSetAttribute(nv_partial, cudaFuncAttributeMaxDynamicSharedMemorySize, smem3);
  cudaFuncSetAttribute(ly_kernel,  cudaFuncAttributeMaxDynamicSharedMemorySize, smem3);
  cudaFuncSetAttribute((const void*)gemm_tf32<3072,1>, cudaFuncAttributeMaxDynamicSharedMemorySize, GEMM_SMEM);
  cudaFuncSetAttribute((const void*)gemm_tf32<1024,0>, cudaFuncAttributeMaxDynamicSharedMemorySize, GEMM_SMEM);

  float* dX;  cudaGetSymbolAddress((void**)&dX,  g_X);
  float* dWaT; cudaGetSymbolAddress((void**)&dWaT, g_WaT);
  float* dWpT; cudaGetSymbolAddress((void**)&dWpT, g_WpT);
  round_permute_kernel<<<(BATCH*TLEN*CDIM/8 + 255)/256, 256>>>((const float4*)x, (float4*)dX, BATCH*TLEN*CDIM/8);
  transpose_rp_kernel<<<dim3(3*CDIM/32, CDIM/32), 256>>>(Wa, dWaT, 3*CDIM);
  transpose_rp_kernel<<<dim3(CDIM/32, CDIM/32), 256>>>(Wp, dWpT, CDIM);

  gemm_tf32<3072,1><<<dim3(24, 128), 128, GEMM_SMEM>>>(nullptr);
  landmarks_kernel<<<dim3(NLM, BH), 64>>>();
  nv_partial<<<dim3(8, BH), 256, smem3>>>();
  ns_combine_z_kernel<<<BH, 256, smem5>>>();
  ly_kernel<<<dim3(64, BH), 256, smem3>>>();
  gemm_tf32<1024,0><<<dim3(8, 128), 128, GEMM_SMEM>>>(out);
}

// round 16
// speedup vs baseline: 1.1272x; 1.0069x over previous
#include <cuda_runtime.h>
#include <math.h>
#include <stdint.h>

// ---------------- Problem constants ----------------
#define NHEAD 16
#define HS    64
#define NLM   64
#define TLEN  4096
#define BATCH 4
#define BH    64
#define CDIM  1024
#define HEAD_ELEMS (TLEN*HS)
#define QKV_ELEMS  (BH*HEAD_ELEMS)
#define SSTR  65

// ---------------- Scratch ----------------
__device__ float g_Q[QKV_ELEMS];
__device__ float g_K[QKV_ELEMS];
__device__ float g_V[QKV_ELEMS];
__device__ float g_ql[BH*NLM*HS];
__device__ float g_kl[BH*NLM*HS];
__device__ float g_NVp[BH*8*NLM*HS];
__device__ float g_mp [BH*8*NLM];
__device__ float g_sp [BH*8*NLM];
__device__ float g_Z  [BH*NLM*HS];
__device__ float g_Y  [BATCH*TLEN*CDIM];   // tf32-rounded, k-permuted (GEMM2 A)
__device__ float g_X  [BATCH*TLEN*CDIM];   // tf32-rounded, k-permuted (GEMM1 A)
__device__ float g_WaT[3*CDIM*CDIM];       // W_attn^T [n][k], tf32-rounded, k-permuted
__device__ float g_WpT[CDIM*CDIM];         // W_proj^T [n][k], tf32-rounded, k-permuted

// ======================= tf32 helpers ======================================
__device__ __forceinline__ uint32_t f2tf32(float x) {
  uint32_t u;
  asm("cvt.rna.tf32.f32 %0, %1;" : "=r"(u) : "f"(x));
  return u;
}
__device__ __forceinline__ void mma_tf32(float c[4], uint32_t a0, uint32_t a1,
                                         uint32_t a2, uint32_t a3,
                                         uint32_t b0, uint32_t b1) {
  asm volatile(
    "mma.sync.aligned.m16n8k8.row.col.f32.tf32.tf32.f32 "
    "{%0,%1,%2,%3}, {%4,%5,%6,%7}, {%8,%9}, {%0,%1,%2,%3};"
    : "+f"(c[0]), "+f"(c[1]), "+f"(c[2]), "+f"(c[3])
    : "r"(a0), "r"(a1), "r"(a2), "r"(a3), "r"(b0), "r"(b1));
}
__device__ __forceinline__ void cp_async16(void* smem_dst, const void* gsrc) {
  uint32_t s = (uint32_t)__cvta_generic_to_shared(smem_dst);
  asm volatile("cp.async.ca.shared.global [%0], [%1], 16;\n" :: "r"(s), "l"(gsrc));
}
#define CP_COMMIT() asm volatile("cp.async.commit_group;\n" ::: "memory")
#define CP_WAIT(n)  asm volatile("cp.async.wait_group %0;\n" :: "n"(n) : "memory")

// ---------------- pre-round + k-group permute (for A inputs) ----------------
__global__ __launch_bounds__(256) void round_permute_kernel(const float4* __restrict__ src,
                                                            float4* __restrict__ dst, int n8) {
  int i = blockIdx.x * blockDim.x + threadIdx.x;
  if (i < n8) {
    float4 v0 = src[2*i];
    float4 v1 = src[2*i + 1];
    float4 w0, w1;
    w0.x = __uint_as_float(f2tf32(v0.x));
    w0.y = __uint_as_float(f2tf32(v1.x));
    w0.z = __uint_as_float(f2tf32(v0.y));
    w0.w = __uint_as_float(f2tf32(v1.y));
    w1.x = __uint_as_float(f2tf32(v0.z));
    w1.y = __uint_as_float(f2tf32(v1.z));
    w1.z = __uint_as_float(f2tf32(v0.w));
    w1.w = __uint_as_float(f2tf32(v1.w));
    dst[2*i] = w0;
    dst[2*i + 1] = w1;
  }
}

// ---------------- transpose + round + k-permute (for B weights) ------------
__global__ __launch_bounds__(256) void transpose_rp_kernel(const float* __restrict__ src,
                                                           float* __restrict__ dst, int ND) {
  __shared__ float t[32][33];
  const int KD = 1024;
  int n0 = blockIdx.x * 32, k0 = blockIdx.y * 32;
  int tx = threadIdx.x & 31, ty8 = threadIdx.x >> 5;
#pragma unroll
  for (int r = 0; r < 4; r++) {
    int k = k0 + ty8 + r*8;
    t[ty8 + r*8][tx] = __uint_as_float(f2tf32(src[(size_t)k*ND + n0 + tx]));
  }
  __syncthreads();
#pragma unroll
  for (int r = 0; r < 4; r++) {
    int n = n0 + ty8 + r*8;
    int c = tx & 7;
    int kpos = (tx & ~7) + 2*(c & 3) + (c >> 2);
    dst[(size_t)n*KD + k0 + kpos] = t[tx][ty8 + r*8];
  }
}

// ---------------- GEMM (R12 proven: 128x128, 4 warps 64x64, single-sync) ---
#define TSTR 40
#define T_BUF (128*TSTR)
#define GEMM_SMEM (4*T_BUF*4)

template <int N, int MODE>
__global__ __launch_bounds__(128, 2) void gemm_tf32(float* __restrict__ Cout) {
  extern __shared__ float sm[];
  float* As[2] = { sm,           sm + T_BUF };
  float* Bs[2] = { sm + 2*T_BUF, sm + 3*T_BUF };

  const float* A  = (MODE == 1) ? (const float*)g_X   : (const float*)g_Y;
  const float* Bt = (MODE == 1) ? (const float*)g_WaT : (const float*)g_WpT;

  const int K = 1024;
  const int tid = threadIdx.x;
  const int warp = tid >> 5, lane = tid & 31;
  const int wm = warp >> 1, wn = warp & 1;
  const int g = lane >> 2, tg = lane & 3;

  const float* Ap = A  + (size_t)(blockIdx.y * 128) * K;
  const float* Bp = Bt + (size_t)(blockIdx.x * 128) * K;

  float acc[4][8][4];
#pragma unroll
  for (int i = 0; i < 4; i++)
#pragma unroll
    for (int j = 0; j < 8; j++)
#pragma unroll
      for (int r = 0; r < 4; r++) acc[i][j][r] = 0.f;

  const int cr = tid >> 3;
  const int cs = (tid & 7) * 4;

  auto load_tile = [&](int kt, int buf) {
    const int k0 = kt * 32;
#pragma unroll
    for (int i = 0; i < 8; i++) {
      int row = cr + i * 16;
      cp_async16(As[buf] + row*TSTR + cs, Ap + (size_t)row * K + k0 + cs);
      cp_async16(Bs[buf] + row*TSTR + cs, Bp + (size_t)row * K + k0 + cs);
    }
    CP_COMMIT();
  };

  load_tile(0, 0);
  const int NT = K / 32;
  for (int kt = 0; kt < NT; kt++) {
    CP_WAIT(0);
    __syncthreads();
    if (kt + 1 < NT) load_tile(kt + 1, (kt + 1) & 1);
    const float* Ab = As[kt & 1];
    const float* Bb = Bs[kt & 1];
#pragma unroll
    for (int ks = 0; ks < 4; ks++) {
      const int kp = ks * 8 + 2 * tg;
      uint32_t bf[8][2];
#pragma unroll
      for (int nt = 0; nt < 8; nt++) {
        int nb = wn * 64 + nt * 8 + g;
        float2 b2 = *(const float2*)&Bb[nb * TSTR + kp];
        bf[nt][0] = __float_as_uint(b2.x);
        bf[nt][1] = __float_as_uint(b2.y);
      }
#pragma unroll
      for (int mt = 0; mt < 4; mt++) {
        int rm = wm * 64 + mt * 16;
        float2 alo = *(const float2*)&Ab[(rm + g    ) * TSTR + kp];
        float2 ahi = *(const float2*)&Ab[(rm + g + 8) * TSTR + kp];
        uint32_t a0 = __float_as_uint(alo.x);
        uint32_t a1 = __float_as_uint(ahi.x);
        uint32_t a2 = __float_as_uint(alo.y);
        uint32_t a3 = __float_as_uint(ahi.y);
#pragma unroll
        for (int nt = 0; nt < 8; nt++)
          mma_tf32(acc[mt][nt], a0, a1, a2, a3, bf[nt][0], bf[nt][1]);
      }
    }
  }

#pragma unroll
  for (int mt = 0; mt < 4; mt++) {
#pragma unroll
    for (int nt = 0; nt < 8; nt++) {
      int row = blockIdx.y * 128 + wm * 64 + mt * 16 + g;
      int col = blockIdx.x * 128 + wn * 64 + nt * 8 + 2 * tg;
      if (MODE == 0) {
        float* p0 = Cout + (size_t)row * N + col;
        float* p1 = Cout + (size_t)(row + 8) * N + col;
        *(float2*)p0 = make_float2(acc[mt][nt][0], acc[mt][nt][1]);
        *(float2*)p1 = make_float2(acc[mt][nt][2], acc[mt][nt][3]);
      } else {
        int which = col >> 10;
        int h = (col >> 6) & 15, d = col & 63;
        float* dst = (which == 0) ? g_Q : ((which == 1) ? g_K : g_V);
        int b0 = row >> 12, t0 = row & 4095;
        float* p0 = dst + ((size_t)((b0 * NHEAD + h) * TLEN + t0)) * HS + d;
        int rowb = row + 8;
        int b1 = rowb >> 12, t1 = rowb & 4095;
        float* p1 = dst + ((size_t)((b1 * NHEAD + h) * TLEN + t1)) * HS + d;
        *(float2*)p0 = make_float2(acc[mt][nt][0], acc[mt][nt][1]);
        *(float2*)p1 = make_float2(acc[mt][nt][2], acc[mt][nt][3]);
      }
    }
  }
}

// ---------------- 64x64 tile helpers: strided ownership ----------
__device__ __forceinline__ void mm_regs_AB(float acc[4][4], const float* __restrict__ A,
                                           const float* __restrict__ B, int ty, int tx) {
#pragma unroll
  for (int i = 0; i < 4; i++)
#pragma unroll
    for (int j = 0; j < 4; j++) acc[i][j] = 0.f;
  for (int k = 0; k < 64; k++) {
    float a0 = A[(ty   )*SSTR+k], a1 = A[(ty+16)*SSTR+k];
    float a2 = A[(ty+32)*SSTR+k], a3 = A[(ty+48)*SSTR+k];
    float b0 = B[k*SSTR+tx   ], b1 = B[k*SSTR+tx+16];
    float b2 = B[k*SSTR+tx+32], b3 = B[k*SSTR+tx+48];
    acc[0][0]=fmaf(a0,b0,acc[0][0]); acc[0][1]=fmaf(a0,b1,acc[0][1]);
    acc[0][2]=fmaf(a0,b2,acc[0][2]); acc[0][3]=fmaf(a0,b3,acc[0][3]);
    acc[1][0]=fmaf(a1,b0,acc[1][0]); acc[1][1]=fmaf(a1,b1,acc[1][1]);
    acc[1][2]=fmaf(a1,b2,acc[1][2]); acc[1][3]=fmaf(a1,b3,acc[1][3]);
    acc[2][0]=fmaf(a2,b0,acc[2][0]); acc[2][1]=fmaf(a2,b1,acc[2][1]);
    acc[2][2]=fmaf(a2,b2,acc[2][2]); acc[2][3]=fmaf(a2,b3,acc[2][3]);
    acc[3][0]=fmaf(a3,b0,acc[3][0]); acc[3][1]=fmaf(a3,b1,acc[3][1]);
    acc[3][2]=fmaf(a3,b2,acc[3][2]); acc[3][3]=fmaf(a3,b3,acc[3][3]);
  }
}
__device__ __forceinline__ void mm_acc_AB(float acc[4][4], const float* __restrict__ A,
                                          const float* __restrict__ B, int ty, int tx) {
  for (int k = 0; k < 64; k++) {
    float a0 = A[(ty   )*SSTR+k], a1 = A[(ty+16)*SSTR+k];
    float a2 = A[(ty+32)*SSTR+k], a3 = A[(ty+48)*SSTR+k];
    float b0 = B[k*SSTR+tx   ], b1 = B[k*SSTR+tx+16];
    float b2 = B[k*SSTR+tx+32], b3 = B[k*SSTR+tx+48];
    acc[0][0]=fmaf(a0,b0,acc[0][0]); acc[0][1]=fmaf(a0,b1,acc[0][1]);
    acc[0][2]=fmaf(a0,b2,acc[0][2]); acc[0][3]=fmaf(a0,b3,acc[0][3]);
    acc[1][0]=fmaf(a1,b0,acc[1][0]); acc[1][1]=fmaf(a1,b1,acc[1][1]);
    acc[1][2]=fmaf(a1,b2,acc[1][2]); acc[1][3]=fmaf(a1,b3,acc[1][3]);
    acc[2][0]=fmaf(a2,b0,acc[2][0]); acc[2][1]=fmaf(a2,b1,acc[2][1]);
    acc[2][2]=fmaf(a2,b2,acc[2][2]); acc[2][3]=fmaf(a2,b3,acc[2][3]);
    acc[3][0]=fmaf(a3,b0,acc[3][0]); acc[3][1]=fmaf(a3,b1,acc[3][1]);
    acc[3][2]=fmaf(a3,b2,acc[3][2]); acc[3][3]=fmaf(a3,b3,acc[3][3]);
  }
}
__device__ __forceinline__ void mm_regs_ABt(float acc[4][4], const float* __restrict__ A,
                                            const float* __restrict__ B, int ty, int tx) {
#pragma unroll
  for (int i = 0; i < 4; i++)
#pragma unroll
    for (int j = 0; j < 4; j++) acc[i][j] = 0.f;
  for (int d = 0; d < 64; d++) {
    float a0 = A[(ty   )*SSTR+d], a1 = A[(ty+16)*SSTR+d];
    float a2 = A[(ty+32)*SSTR+d], a3 = A[(ty+48)*SSTR+d];
    float b0 = B[(tx   )*SSTR+d], b1 = B[(tx+16)*SSTR+d];
    float b2 = B[(tx+32)*SSTR+d], b3 = B[(tx+48)*SSTR+d];
    acc[0][0]=fmaf(a0,b0,acc[0][0]); acc[0][1]=fmaf(a0,b1,acc[0][1]);
    acc[0][2]=fmaf(a0,b2,acc[0][2]); acc[0][3]=fmaf(a0,b3,acc[0][3]);
    acc[1][0]=fmaf(a1,b0,acc[1][0]); acc[1][1]=fmaf(a1,b1,acc[1][1]);
    acc[1][2]=fmaf(a1,b2,acc[1][2]); acc[1][3]=fmaf(a1,b3,acc[1][3]);
    acc[2][0]=fmaf(a2,b0,acc[2][0]); acc[2][1]=fmaf(a2,b1,acc[2][1]);
    acc[2][2]=fmaf(a2,b2,acc[2][2]); acc[2][3]=fmaf(a2,b3,acc[2][3]);
    acc[3][0]=fmaf(a3,b0,acc[3][0]); acc[3][1]=fmaf(a3,b1,acc[3][1]);
    acc[3][2]=fmaf(a3,b2,acc[3][2]); acc[3][3]=fmaf(a3,b3,acc[3][3]);
  }
}
__device__ __forceinline__ void mm_store_AB(float* __restrict__ C, const float* __restrict__ A,
                                            const float* __restrict__ B, int ty, int tx) {
  float acc[4][4];
  mm_regs_AB(acc, A, B, ty, tx);
#pragma unroll
  for (int i = 0; i < 4; i++)
#pragma unroll
    for (int j = 0; j < 4; j++) C[(ty+16*i)*SSTR + tx + 16*j] = acc[i][j];
}
__device__ __forceinline__ float rowmax16(float v) {
#pragma unroll
  for (int off = 8; off; off >>= 1)
    v = fmaxf(v, __shfl_xor_sync(0xffffffffu, v, off, 16));
  return v;
}
__device__ __forceinline__ float rowsum16(float v) {
#pragma unroll
  for (int off = 8; off; off >>= 1)
    v += __shfl_xor_sync(0xffffffffu, v, off, 16);
  return v;
}
// float4 gmem -> scalar smem tile copy (rows of 64, SSTR-strided dest)
__device__ __forceinline__ void tile_load64(float* __restrict__ dst,
                                            const float* __restrict__ src, int tid) {
#pragma unroll
  for (int it = 0; it < 4; it++) {
    int e = (tid + it*256) * 4;
    float4 v = *(const float4*)(src + e);
    float* p = &dst[(e >> 6)*SSTR + (e & 63)];
    p[0] = v.x; p[1] = v.y; p[2] = v.z; p[3] = v.w;
  }
}

// ---------------- Landmarks ----------------
__global__ void landmarks_kernel() {
  const int bh = blockIdx.y, l = blockIdx.x, d = threadIdx.x;
  const float* qb = g_Q + (size_t)bh * HEAD_ELEMS + (size_t)l * 64 * HS;
  const float* kb = g_K + (size_t)bh * HEAD_ELEMS + (size_t)l * 64 * HS;
  float sq = 0.f, sk = 0.f;
  for (int tt = 0; tt < 64; tt++) { sq += qb[tt*HS + d]; sk += kb[tt*HS + d]; }
  g_ql[bh*NLM*HS + l*HS + d] = sq * (1.f/64.f);
  g_kl[bh*NLM*HS + l*HS + d] = sk * (1.f/64.f);
}

// ---------------- NV partial ----------------
__global__ __launch_bounds__(256) void nv_partial() {
  extern __shared__ float sm[];
  float* sql = sm;
  float* skP = sm + 4160;
  float* sv  = sm + 2*4160;
  const int bh = blockIdx.y, ts = blockIdx.x;
  const int tid = threadIdx.x, ty = tid >> 4, tx = tid & 15;
  const float* Kb = g_K + (size_t)bh * HEAD_ELEMS;
  const float* Vb = g_V + (size_t)bh * HEAD_ELEMS;

  tile_load64(sql, g_ql + bh*4096, tid);

  float rowm[4], rsum[4], acc[4][4];
#pragma unroll
  for (int i = 0; i < 4; i++) {
    rowm[i] = -1e30f; rsum[i] = 0.f;
#pragma unroll
    for (int j = 0; j < 4; j++) acc[i][j] = 0.f;
  }
  __syncthreads();
  const int tbase = ts * 512;
  for (int c = 0; c < 8; c++) {
    const int t0 = tbase + c * 64;
    tile_load64(skP, Kb + (size_t)t0 * 64, tid);
    tile_load64(sv,  Vb + (size_t)t0 * 64, tid);
    __syncthreads();
    float s[4][4];
    mm_regs_ABt(s, sql, skP, ty, tx);
#pragma unroll
    for (int i = 0; i < 4; i++) {
      float mx = fmaxf(fmaxf(s[i][0], s[i][1]), fmaxf(s[i][2], s[i][3]));
      mx = rowmax16(mx);
      float nm = fmaxf(rowm[i], mx);
      float al = __expf(rowm[i] - nm);
      rowm[i] = nm;
#pragma unroll
      for (int j = 0; j < 4; j++) s[i][j] = __expf(s[i][j] - nm);
      float ls = s[i][0] + s[i][1] + s[i][2] + s[i][3];
      ls = rowsum16(ls);
      rsum[i] = rsum[i] * al + ls;
#pragma unroll
      for (int j = 0; j < 4; j++) acc[i][j] *= al;
    }
    __syncthreads();
#pragma unroll
    for (int i = 0; i < 4; i++)
#pragma unroll
      for (int j = 0; j < 4; j++) skP[(ty+16*i)*SSTR + tx + 16*j] = s[i][j];
    __syncthreads();
    mm_acc_AB(acc, skP, sv, ty, tx);
    __syncthreads();
  }
  const size_t pb = (size_t)(bh*8 + ts) * 4096;
#pragma unroll
  for (int i = 0; i < 4; i++)
#pragma unroll
    for (int j = 0; j < 4; j++)
      g_NVp[pb + (ty+16*i)*64 + tx + 16*j] = acc[i][j];
  if (tx == 0) {
#pragma unroll
    for (int i = 0; i < 4; i++) {
      g_mp[(bh*8 + ts)*64 + ty + 16*i] = rowm[i];
      g_sp[(bh*8 + ts)*64 + ty + 16*i] = rsum[i];
    }
  }
}

// ---------------- FUSED: Newton-Schulz + combine + Z --------------------
__global__ __launch_bounds__(256) void ns_combine_z_kernel() {
  extern __shared__ float sm[];
  float* sK  = sm;
  float* sV  = sm + 4160;          // ends as P
  float* sKV = sm + 2*4160;        // reused as NV for combine
  float* sT  = sm + 3*4160;
  float* sU  = sm + 4*4160;
  __shared__ float scol[64];
  __shared__ float sden;
  __shared__ float W[8][64];
  __shared__ float D[64];
  const int bh = blockIdx.x;
  const int tid = threadIdx.x;
  const int ty = tid >> 4, tx = tid & 15;

  tile_load64(sT, g_ql + bh*4096, tid);
  tile_load64(sU, g_kl + bh*4096, tid);
  __syncthreads();
  {
    float acc[4][4];
    mm_regs_ABt(acc, sT, sU, ty, tx);
#pragma unroll
    for (int i = 0; i < 4; i++)
#pragma unroll
      for (int j = 0; j < 4; j++) sK[(ty+16*i)*SSTR + tx + 16*j] = acc[i][j];
  }
  __syncthreads();
  if (tid < 64) {
    float m = -1e30f;
    for (int j = 0; j < 64; j++) m = fmaxf(m, sK[tid*SSTR + j]);
    float s = 0.f;
    for (int j = 0; j < 64; j++) { float e_ = __expf(sK[tid*SSTR + j] - m); sK[tid*SSTR + j] = e_; s += e_; }
    float inv = 1.f / s;
    for (int j = 0; j < 64; j++) sK[tid*SSTR + j] *= inv;
  }
  __syncthreads();
  if (tid < 64) {
    float cs = 0.f;
    for (int i = 0; i < 64; i++) cs += sK[i*SSTR + tid];
    scol[tid] = cs;
  }
  __syncthreads();
  if (tid == 0) {
    float mx = scol[0];
    for (int j = 1; j < 64; j++) mx = fmaxf(mx, scol[j]);
    sden = mx;
  }
  __syncthreads();
  const float invden = 1.f / sden;
  for (int e = tid; e < 4096; e += 256) {
    int i = e >> 6, j = e & 63;
    sV[i*SSTR + j] = sK[j*SSTR + i] * invden;
  }
  __syncthreads();
  for (int it = 0; it < 6; it++) {
    mm_store_AB(sKV, sK, sV, ty, tx); __syncthreads();
    for (int e = tid; e < 4096; e += 256) {
      int i = e >> 6, j = e & 63;
      sT[i*SSTR + j] = ((i == j) ? 7.f : 0.f) - sKV[i*SSTR + j];
    }
    __syncthreads();
    mm_store_AB(sU, sKV, sT, ty, tx); __syncthreads();
    for (int e = tid; e < 4096; e += 256) {
      int i = e >> 6, j = e & 63;
      sT[i*SSTR + j] = ((i == j) ? 15.f : 0.f) - sU[i*SSTR + j];
    }
    __syncthreads();
    mm_store_AB(sU, sKV, sT, ty, tx); __syncthreads();
    for (int e = tid; e < 4096; e += 256) {
      int i = e >> 6, j = e & 63;
      sT[i*SSTR + j] = ((i == j) ? 13.f : 0.f) - sU[i*SSTR + j];
    }
    __syncthreads();
    mm_store_AB(sU, sV, sT, ty, tx); __syncthreads();
    for (int e = tid; e < 4096; e += 256) {
      int i = e >> 6, j = e & 63;
      sV[i*SSTR + j] = 0.25f * sU[i*SSTR + j];
    }
    __syncthreads();
  }
  // sV now holds P.

  // ---- combine: NV into sKV ----
  if (tid < 64) {
    float mp[8];
    float m = -1e30f;
    for (int p = 0; p < 8; p++) { mp[p] = g_mp[(bh*8 + p)*64 + tid]; m = fmaxf(m, mp[p]); }
    float dd = 0.f;
    for (int p = 0; p < 8; p++) {
      float w = __expf(mp[p] - m);
      W[p][tid] = w;
      dd += g_sp[(bh*8 + p)*64 + tid] * w;
    }
    D[tid] = dd;
  }
  __syncthreads();
  for (int e = tid; e < 4096; e += 256) {
    int l = e >> 6, d = e & 63;
    float v = 0.f;
    for (int p = 0; p < 8; p++)
      v += g_NVp[(size_t)(bh*8 + p)*4096 + e] * W[p][l];
    sKV[l*SSTR + d] = v / D[l];
  }
  __syncthreads();

  // ---- Z = P @ NV ----
  float acc[4][4];
  mm_regs_AB(acc, sV, sKV, ty, tx);
#pragma unroll
  for (int i = 0; i < 4; i++)
#pragma unroll
    for (int j = 0; j < 4; j++)
      g_Z[bh*4096 + (ty+16*i)*64 + tx + 16*j] = acc[i][j];
}

// ---------------- Y = softmax(q @ k_l^T) @ Z, rounded + k-permuted ---------
__global__ __launch_bounds__(256) void ly_kernel() {
  extern __shared__ float sm[];
  float* sqP = sm;
  float* skl = sm + 4160;
  float* sZ  = sm + 2*4160;
  const int bh = blockIdx.y, tt = blockIdx.x;
  const int tid = threadIdx.x, ty = tid >> 4, tx = tid & 15;
  const int t0 = tt * 64;
  const float* Qb = g_Q + (size_t)bh * HEAD_ELEMS + (size_t)t0 * 64;
  tile_load64(sqP, Qb, tid);
  tile_load64(skl, g_kl + bh*4096, tid);
  tile_load64(sZ,  g_Z  + bh*4096, tid);
  __syncthreads();
  float s[4][4];
  mm_regs_ABt(s, sqP, skl, ty, tx);
  float rs[4];
#pragma unroll
  for (int i = 0; i < 4; i++) {
    float mx = fmaxf(fmaxf(s[i][0], s[i][1]), fmaxf(s[i][2], s[i][3]));
    mx = rowmax16(mx);
#pragma unroll
    for (int j = 0; j < 4; j++) s[i][j] = __expf(s[i][j] - mx);
    float ls = s[i][0] + s[i][1] + s[i][2] + s[i][3];
    rs[i] = rowsum16(ls);
  }
  __syncthreads();
#pragma unroll
  for (int i = 0; i < 4; i++)
#pragma unroll
    for (int j = 0; j < 4; j++) sqP[(ty+16*i)*SSTR + tx + 16*j] = s[i][j];
  __syncthreads();
  float acc[4][4];
  mm_regs_AB(acc, sqP, sZ, ty, tx);
  const int b = bh >> 4, h = bh & 15;
  const int w = tx & 7;
  const int cbase = h*HS + (tx & ~7) + 2*(w & 3) + (w >> 2);
#pragma unroll
  for (int i = 0; i < 4; i++) {
    float inv = 1.f / rs[i];
    float* prow = g_Y + (size_t)(b*TLEN + t0 + ty + 16*i) * CDIM;
#pragma unroll
    for (int j = 0; j < 4; j++) {
      float v = __uint_as_float(f2tf32(acc[i][j] * inv));
      prow[cbase + 16*j] = v;
    }
  }
}

// ---------------- Launch ----------------
extern "C" void kernel_launch(void* const* d_in, const int* in_sizes, int n_in,
                              void* d_out, int out_size) {
  const float* x  = (const float*)d_in[0];
  const float* Wa = (const float*)d_in[1];
  const float* Wp = (const float*)d_in[2];
  float* out = (float*)d_out;

  const int smem5 = 5 * 4160 * 4;
  const int smem3 = 3 * 4160 * 4;
  cudaFuncSetAttribute(ns_combine_z_kernel, cudaFuncAttributeMaxDynamicSharedMemorySize, smem5);
  cudaFuncSetAttribute(nv_partial, cudaFuncAttributeMaxDynamicSharedMemorySize, smem3);
  cudaFuncSetAttribute(ly_kernel,  cudaFuncAttributeMaxDynamicSharedMemorySize, smem3);
  cudaFuncSetAttribute((const void*)gemm_tf32<3072,1>, cudaFuncAttributeMaxDynamicSharedMemorySize, GEMM_SMEM);
  cudaFuncSetAttribute((const void*)gemm_tf32<1024,0>, cudaFuncAttributeMaxDynamicSharedMemorySize, GEMM_SMEM);

  float* dX;  cudaGetSymbolAddress((void**)&dX,  g_X);
  float* dWaT; cudaGetSymbolAddress((void**)&dWaT, g_WaT);
  float* dWpT; cudaGetSymbolAddress((void**)&dWpT, g_WpT);
  round_permute_kernel<<<(BATCH*TLEN*CDIM/8 + 255)/256, 256>>>((const float4*)x, (float4*)dX, BATCH*TLEN*CDIM/8);
  transpose_rp_kernel<<<dim3(3*CDIM/32, CDIM/32), 256>>>(Wa, dWaT, 3*CDIM);
  transpose_rp_kernel<<<dim3(CDIM/32, CDIM/32), 256>>>(Wp, dWpT, CDIM);

  gemm_tf32<3072,1><<<dim3(24, 128), 128, GEMM_SMEM>>>(nullptr);
  landmarks_kernel<<<dim3(NLM, BH), 64>>>();
  nv_partial<<<dim3(8, BH), 256, smem3>>>();
  ns_combine_z_kernel<<<BH, 256, smem5>>>();
  ly_kernel<<<dim3(64, BH), 256, smem3>>>();
  gemm_tf32<1024,0><<<dim3(8, 128), 128, GEMM_SMEM>>>(out);
}

// round 17
// speedup vs baseline: 1.2281x; 1.0895x over previous
#include <cuda_runtime.h>
#include <math.h>
#include <stdint.h>

// ---------------- Problem constants ----------------
#define NHEAD 16
#define HS    64
#define NLM   64
#define TLEN  4096
#define BATCH 4
#define BH    64
#define CDIM  1024
#define HEAD_ELEMS (TLEN*HS)
#define QKV_ELEMS  (BH*HEAD_ELEMS)
#define SSTR  66
#define TILE  (64*SSTR)   // 4224 floats

// ---------------- Scratch ----------------
__device__ float g_Q[QKV_ELEMS];
__device__ float g_K[QKV_ELEMS];
__device__ float g_V[QKV_ELEMS];
__device__ float g_ql[BH*NLM*HS];
__device__ float g_kl[BH*NLM*HS];
__device__ float g_NVp[BH*8*NLM*HS];
__device__ float g_mp [BH*8*NLM];
__device__ float g_sp [BH*8*NLM];
__device__ float g_Z  [BH*NLM*HS];
__device__ float g_Y  [BATCH*TLEN*CDIM];   // tf32-rounded, k-permuted (GEMM2 A)
__device__ float g_X  [BATCH*TLEN*CDIM];   // tf32-rounded, k-permuted (GEMM1 A)
__device__ float g_WaT[3*CDIM*CDIM];
__device__ float g_WpT[CDIM*CDIM];

// ======================= tf32 helpers ======================================
__device__ __forceinline__ uint32_t f2tf32(float x) {
  uint32_t u;
  asm("cvt.rna.tf32.f32 %0, %1;" : "=r"(u) : "f"(x));
  return u;
}
__device__ __forceinline__ void mma_tf32(float c[4], uint32_t a0, uint32_t a1,
                                         uint32_t a2, uint32_t a3,
                                         uint32_t b0, uint32_t b1) {
  asm volatile(
    "mma.sync.aligned.m16n8k8.row.col.f32.tf32.tf32.f32 "
    "{%0,%1,%2,%3}, {%4,%5,%6,%7}, {%8,%9}, {%0,%1,%2,%3};"
    : "+f"(c[0]), "+f"(c[1]), "+f"(c[2]), "+f"(c[3])
    : "r"(a0), "r"(a1), "r"(a2), "r"(a3), "r"(b0), "r"(b1));
}
__device__ __forceinline__ void cp_async16(void* smem_dst, const void* gsrc) {
  uint32_t s = (uint32_t)__cvta_generic_to_shared(smem_dst);
  asm volatile("cp.async.ca.shared.global [%0], [%1], 16;\n" :: "r"(s), "l"(gsrc));
}
#define CP_COMMIT() asm volatile("cp.async.commit_group;\n" ::: "memory")
#define CP_WAIT(n)  asm volatile("cp.async.wait_group %0;\n" :: "n"(n) : "memory")

// ---------------- pre-round + k-group permute (for A inputs) ----------------
__global__ __launch_bounds__(256) void round_permute_kernel(const float4* __restrict__ src,
                                                            float4* __restrict__ dst, int n8) {
  int i = blockIdx.x * blockDim.x + threadIdx.x;
  if (i < n8) {
    float4 v0 = src[2*i];
    float4 v1 = src[2*i + 1];
    float4 w0, w1;
    w0.x = __uint_as_float(f2tf32(v0.x));
    w0.y = __uint_as_float(f2tf32(v1.x));
    w0.z = __uint_as_float(f2tf32(v0.y));
    w0.w = __uint_as_float(f2tf32(v1.y));
    w1.x = __uint_as_float(f2tf32(v0.z));
    w1.y = __uint_as_float(f2tf32(v1.z));
    w1.z = __uint_as_float(f2tf32(v0.w));
    w1.w = __uint_as_float(f2tf32(v1.w));
    dst[2*i] = w0;
    dst[2*i + 1] = w1;
  }
}

// ---------------- transpose + round + k-permute (for B weights) ------------
__global__ __launch_bounds__(256) void transpose_rp_kernel(const float* __restrict__ src,
                                                           float* __restrict__ dst, int ND) {
  __shared__ float t[32][33];
  const int KD = 1024;
  int n0 = blockIdx.x * 32, k0 = blockIdx.y * 32;
  int tx = threadIdx.x & 31, ty8 = threadIdx.x >> 5;
#pragma unroll
  for (int r = 0; r < 4; r++) {
    int k = k0 + ty8 + r*8;
    t[ty8 + r*8][tx] = __uint_as_float(f2tf32(src[(size_t)k*ND + n0 + tx]));
  }
  __syncthreads();
#pragma unroll
  for (int r = 0; r < 4; r++) {
    int n = n0 + ty8 + r*8;
    int c = tx & 7;
    int kpos = (tx & ~7) + 2*(c & 3) + (c >> 2);
    dst[(size_t)n*KD + k0 + kpos] = t[tx][ty8 + r*8];
  }
}

// ---------------- GEMM (R12 proven) ----------------
#define TSTR 40
#define T_BUF (128*TSTR)
#define GEMM_SMEM (4*T_BUF*4)

template <int N, int MODE>
__global__ __launch_bounds__(128, 2) void gemm_tf32(float* __restrict__ Cout) {
  extern __shared__ float sm[];
  float* As[2] = { sm,           sm + T_BUF };
  float* Bs[2] = { sm + 2*T_BUF, sm + 3*T_BUF };

  const float* A  = (MODE == 1) ? (const float*)g_X   : (const float*)g_Y;
  const float* Bt = (MODE == 1) ? (const float*)g_WaT : (const float*)g_WpT;

  const int K = 1024;
  const int tid = threadIdx.x;
  const int warp = tid >> 5, lane = tid & 31;
  const int wm = warp >> 1, wn = warp & 1;
  const int g = lane >> 2, tg = lane & 3;

  const float* Ap = A  + (size_t)(blockIdx.y * 128) * K;
  const float* Bp = Bt + (size_t)(blockIdx.x * 128) * K;

  float acc[4][8][4];
#pragma unroll
  for (int i = 0; i < 4; i++)
#pragma unroll
    for (int j = 0; j < 8; j++)
#pragma unroll
      for (int r = 0; r < 4; r++) acc[i][j][r] = 0.f;

  const int cr = tid >> 3;
  const int cs = (tid & 7) * 4;

  auto load_tile = [&](int kt, int buf) {
    const int k0 = kt * 32;
#pragma unroll
    for (int i = 0; i < 8; i++) {
      int row = cr + i * 16;
      cp_async16(As[buf] + row*TSTR + cs, Ap + (size_t)row * K + k0 + cs);
      cp_async16(Bs[buf] + row*TSTR + cs, Bp + (size_t)row * K + k0 + cs);
    }
    CP_COMMIT();
  };

  load_tile(0, 0);
  const int NT = K / 32;
  for (int kt = 0; kt < NT; kt++) {
    CP_WAIT(0);
    __syncthreads();
    if (kt + 1 < NT) load_tile(kt + 1, (kt + 1) & 1);
    const float* Ab = As[kt & 1];
    const float* Bb = Bs[kt & 1];
#pragma unroll
    for (int ks = 0; ks < 4; ks++) {
      const int kp = ks * 8 + 2 * tg;
      uint32_t bf[8][2];
#pragma unroll
      for (int nt = 0; nt < 8; nt++) {
        int nb = wn * 64 + nt * 8 + g;
        float2 b2 = *(const float2*)&Bb[nb * TSTR + kp];
        bf[nt][0] = __float_as_uint(b2.x);
        bf[nt][1] = __float_as_uint(b2.y);
      }
#pragma unroll
      for (int mt = 0; mt < 4; mt++) {
        int rm = wm * 64 + mt * 16;
        float2 alo = *(const float2*)&Ab[(rm + g    ) * TSTR + kp];
        float2 ahi = *(const float2*)&Ab[(rm + g + 8) * TSTR + kp];
        uint32_t a0 = __float_as_uint(alo.x);
        uint32_t a1 = __float_as_uint(ahi.x);
        uint32_t a2 = __float_as_uint(alo.y);
        uint32_t a3 = __float_as_uint(ahi.y);
#pragma unroll
        for (int nt = 0; nt < 8; nt++)
          mma_tf32(acc[mt][nt], a0, a1, a2, a3, bf[nt][0], bf[nt][1]);
      }
    }
  }

#pragma unroll
  for (int mt = 0; mt < 4; mt++) {
#pragma unroll
    for (int nt = 0; nt < 8; nt++) {
      int row = blockIdx.y * 128 + wm * 64 + mt * 16 + g;
      int col = blockIdx.x * 128 + wn * 64 + nt * 8 + 2 * tg;
      if (MODE == 0) {
        float* p0 = Cout + (size_t)row * N + col;
        float* p1 = Cout + (size_t)(row + 8) * N + col;
        *(float2*)p0 = make_float2(acc[mt][nt][0], acc[mt][nt][1]);
        *(float2*)p1 = make_float2(acc[mt][nt][2], acc[mt][nt][3]);
      } else {
        int which = col >> 10;
        int h = (col >> 6) & 15, d = col & 63;
        float* dst = (which == 0) ? g_Q : ((which == 1) ? g_K : g_V);
        int b0 = row >> 12, t0 = row & 4095;
        float* p0 = dst + ((size_t)((b0 * NHEAD + h) * TLEN + t0)) * HS + d;
        int rowb = row + 8;
        int b1 = rowb >> 12, t1 = rowb & 4095;
        float* p1 = dst + ((size_t)((b1 * NHEAD + h) * TLEN + t1)) * HS + d;
        *(float2*)p0 = make_float2(acc[mt][nt][0], acc[mt][nt][1]);
        *(float2*)p1 = make_float2(acc[mt][nt][2], acc[mt][nt][3]);
      }
    }
  }
}

// ---------------- scalar 64x64 helpers (ns kernel) ----------
__device__ __forceinline__ void mm_regs_AB(float acc[4][4], const float* __restrict__ A,
                                           const float* __restrict__ B, int ty, int tx) {
#pragma unroll
  for (int i = 0; i < 4; i++)
#pragma unroll
    for (int j = 0; j < 4; j++) acc[i][j] = 0.f;
  for (int k = 0; k < 64; k++) {
    float a0 = A[(ty   )*SSTR+k], a1 = A[(ty+16)*SSTR+k];
    float a2 = A[(ty+32)*SSTR+k], a3 = A[(ty+48)*SSTR+k];
    float b0 = B[k*SSTR+tx   ], b1 = B[k*SSTR+tx+16];
    float b2 = B[k*SSTR+tx+32], b3 = B[k*SSTR+tx+48];
    acc[0][0]=fmaf(a0,b0,acc[0][0]); acc[0][1]=fmaf(a0,b1,acc[0][1]);
    acc[0][2]=fmaf(a0,b2,acc[0][2]); acc[0][3]=fmaf(a0,b3,acc[0][3]);
    acc[1][0]=fmaf(a1,b0,acc[1][0]); acc[1][1]=fmaf(a1,b1,acc[1][1]);
    acc[1][2]=fmaf(a1,b2,acc[1][2]); acc[1][3]=fmaf(a1,b3,acc[1][3]);
    acc[2][0]=fmaf(a2,b0,acc[2][0]); acc[2][1]=fmaf(a2,b1,acc[2][1]);
    acc[2][2]=fmaf(a2,b2,acc[2][2]); acc[2][3]=fmaf(a2,b3,acc[2][3]);
    acc[3][0]=fmaf(a3,b0,acc[3][0]); acc[3][1]=fmaf(a3,b1,acc[3][1]);
    acc[3][2]=fmaf(a3,b2,acc[3][2]); acc[3][3]=fmaf(a3,b3,acc[3][3]);
  }
}
__device__ __forceinline__ void mm_regs_ABt(float acc[4][4], const float* __restrict__ A,
                                            const float* __restrict__ B, int ty, int tx) {
#pragma unroll
  for (int i = 0; i < 4; i++)
#pragma unroll
    for (int j = 0; j < 4; j++) acc[i][j] = 0.f;
  for (int d = 0; d < 64; d++) {
    float a0 = A[(ty   )*SSTR+d], a1 = A[(ty+16)*SSTR+d];
    float a2 = A[(ty+32)*SSTR+d], a3 = A[(ty+48)*SSTR+d];
    float b0 = B[(tx   )*SSTR+d], b1 = B[(tx+16)*SSTR+d];
    float b2 = B[(tx+32)*SSTR+d], b3 = B[(tx+48)*SSTR+d];
    acc[0][0]=fmaf(a0,b0,acc[0][0]); acc[0][1]=fmaf(a0,b1,acc[0][1]);
    acc[0][2]=fmaf(a0,b2,acc[0][2]); acc[0][3]=fmaf(a0,b3,acc[0][3]);
    acc[1][0]=fmaf(a1,b0,acc[1][0]); acc[1][1]=fmaf(a1,b1,acc[1][1]);
    acc[1][2]=fmaf(a1,b2,acc[1][2]); acc[1][3]=fmaf(a1,b3,acc[1][3]);
    acc[2][0]=fmaf(a2,b0,acc[2][0]); acc[2][1]=fmaf(a2,b1,acc[2][1]);
    acc[2][2]=fmaf(a2,b2,acc[2][2]); acc[2][3]=fmaf(a2,b3,acc[2][3]);
    acc[3][0]=fmaf(a3,b0,acc[3][0]); acc[3][1]=fmaf(a3,b1,acc[3][1]);
    acc[3][2]=fmaf(a3,b2,acc[3][2]); acc[3][3]=fmaf(a3,b3,acc[3][3]);
  }
}
__device__ __forceinline__ void mm_store_AB(float* __restrict__ C, const float* __restrict__ A,
                                            const float* __restrict__ B, int ty, int tx) {
  float acc[4][4];
  mm_regs_AB(acc, A, B, ty, tx);
#pragma unroll
  for (int i = 0; i < 4; i++)
#pragma unroll
    for (int j = 0; j < 4; j++) C[(ty+16*i)*SSTR + tx + 16*j] = acc[i][j];
}
__device__ __forceinline__ float rowmax16(float v) {
#pragma unroll
  for (int off = 8; off; off >>= 1)
    v = fmaxf(v, __shfl_xor_sync(0xffffffffu, v, off, 16));
  return v;
}
__device__ __forceinline__ float rowsum16(float v) {
#pragma unroll
  for (int off = 8; off; off >>= 1)
    v += __shfl_xor_sync(0xffffffffu, v, off, 16);
  return v;
}
// float4 gmem -> scalar smem tile copy
__device__ __forceinline__ void tile_load64(float* __restrict__ dst,
                                            const float* __restrict__ src, int tid) {
#pragma unroll
  for (int it = 0; it < 4; it++) {
    int e = (tid + it*256) * 4;
    float4 v = *(const float4*)(src + e);
    float* p = &dst[(e >> 6)*SSTR + (e & 63)];
    p[0] = v.x; p[1] = v.y; p[2] = v.z; p[3] = v.w;
  }
}

// ---------------- tensor 64x64x64 fragment helpers (8 warps, 16x32/warp) ---
// ABt: A [m][k] row-major, B [n][k] row-major (i.e., B^T as mma col-major B).
__device__ __forceinline__ void mma64_ABt(float c[4][4], const float* __restrict__ A,
                                          const float* __restrict__ B,
                                          int rm, int cn, int g, int tg) {
#pragma unroll
  for (int nt = 0; nt < 4; nt++)
#pragma unroll
    for (int r = 0; r < 4; r++) c[nt][r] = 0.f;
#pragma unroll
  for (int ks = 0; ks < 8; ks++) {
    const int k8 = ks * 8;
    uint32_t a0 = f2tf32(A[(rm+g  )*SSTR + k8 + tg    ]);
    uint32_t a1 = f2tf32(A[(rm+g+8)*SSTR + k8 + tg    ]);
    uint32_t a2 = f2tf32(A[(rm+g  )*SSTR + k8 + tg + 4]);
    uint32_t a3 = f2tf32(A[(rm+g+8)*SSTR + k8 + tg + 4]);
#pragma unroll
    for (int nt = 0; nt < 4; nt++) {
      int nb = cn + nt*8 + g;
      uint32_t b0 = f2tf32(B[nb*SSTR + k8 + tg    ]);
      uint32_t b1 = f2tf32(B[nb*SSTR + k8 + tg + 4]);
      mma_tf32(c[nt], a0, a1, a2, a3, b0, b1);
    }
  }
}
// AB accumulate: A [m][k] row-major, B [k][n] row-major.
__device__ __forceinline__ void mma64_AB_acc(float c[4][4], const float* __restrict__ A,
                                             const float* __restrict__ B,
                                             int rm, int cn, int g, int tg) {
#pragma unroll
  for (int ks = 0; ks < 8; ks++) {
    const int k8 = ks * 8;
    uint32_t a0 = f2tf32(A[(rm+g  )*SSTR + k8 + tg    ]);
    uint32_t a1 = f2tf32(A[(rm+g+8)*SSTR + k8 + tg    ]);
    uint32_t a2 = f2tf32(A[(rm+g  )*SSTR + k8 + tg + 4]);
    uint32_t a3 = f2tf32(A[(rm+g+8)*SSTR + k8 + tg + 4]);
#pragma unroll
    for (int nt = 0; nt < 4; nt++) {
      int nb = cn + nt*8 + g;
      uint32_t b0 = f2tf32(B[(k8 + tg    )*SSTR + nb]);
      uint32_t b1 = f2tf32(B[(k8 + tg + 4)*SSTR + nb]);
      mma_tf32(c[nt], a0, a1, a2, a3, b0, b1);
    }
  }
}
__device__ __forceinline__ void frag_store(float* __restrict__ S, float c[4][4],
                                           int rm, int cn, int g, int tg) {
#pragma unroll
  for (int nt = 0; nt < 4; nt++) {
    int col = cn + nt*8 + 2*tg;
    *(float2*)&S[(rm+g  )*SSTR + col] = make_float2(c[nt][0], c[nt][1]);
    *(float2*)&S[(rm+g+8)*SSTR + col] = make_float2(c[nt][2], c[nt][3]);
  }
}

// ---------------- Landmarks ----------------
__global__ void landmarks_kernel() {
  const int bh = blockIdx.y, l = blockIdx.x, d = threadIdx.x;
  const float* qb = g_Q + (size_t)bh * HEAD_ELEMS + (size_t)l * 64 * HS;
  const float* kb = g_K + (size_t)bh * HEAD_ELEMS + (size_t)l * 64 * HS;
  float sq = 0.f, sk = 0.f;
  for (int tt = 0; tt < 64; tt++) { sq += qb[tt*HS + d]; sk += kb[tt*HS + d]; }
  g_ql[bh*NLM*HS + l*HS + d] = sq * (1.f/64.f);
  g_kl[bh*NLM*HS + l*HS + d] = sk * (1.f/64.f);
}

// ---------------- NV partial: tensorized S and PV -------------------------
__global__ __launch_bounds__(256) void nv_partial() {
  extern __shared__ float sm[];
  float* sql = sm;
  float* skP = sm + TILE;          // K chunk, then S/P
  float* sv  = sm + 2*TILE;
  __shared__ float alr[64];
  const int bh = blockIdx.y, ts = blockIdx.x;
  const int tid = threadIdx.x, ty = tid >> 4, tx = tid & 15;
  const int warp = tid >> 5, lane = tid & 31;
  const int g = lane >> 2, tg = lane & 3;
  const int rm = (warp >> 1) * 16, cn = (warp & 1) * 32;
  const float* Kb = g_K + (size_t)bh * HEAD_ELEMS;
  const float* Vb = g_V + (size_t)bh * HEAD_ELEMS;

  tile_load64(sql, g_ql + bh*4096, tid);

  float rowm[4], rsum[4];          // stats, (ty,tx) rows ty+16i
  float acc[4][4];                 // PV accum, fragment scheme
#pragma unroll
  for (int i = 0; i < 4; i++) {
    rowm[i] = -1e30f; rsum[i] = 0.f;
#pragma unroll
    for (int j = 0; j < 4; j++) acc[i][j] = 0.f;
  }
  __syncthreads();

  const int tbase = ts * 512;
  for (int c = 0; c < 8; c++) {
    const int t0 = tbase + c * 64;
    tile_load64(skP, Kb + (size_t)t0 * 64, tid);
    tile_load64(sv,  Vb + (size_t)t0 * 64, tid);
    __syncthreads();
    float s[4][4];
    mma64_ABt(s, sql, skP, rm, cn, g, tg);       // S = q_l @ K^T (tensor)
    __syncthreads();                              // K reads done
    frag_store(skP, s, rm, cn, g, tg);            // S -> smem
    __syncthreads();
    // stats + exp in (ty,tx) ownership (same reduction order as before)
#pragma unroll
    for (int i = 0; i < 4; i++) {
      const int row = ty + 16*i;
      float v0 = skP[row*SSTR + tx    ];
      float v1 = skP[row*SSTR + tx + 16];
      float v2 = skP[row*SSTR + tx + 32];
      float v3 = skP[row*SSTR + tx + 48];
      float mx = fmaxf(fmaxf(v0, v1), fmaxf(v2, v3));
      mx = rowmax16(mx);
      float nm = fmaxf(rowm[i], mx);
      float al = __expf(rowm[i] - nm);
      rowm[i] = nm;
      v0 = __expf(v0 - nm); v1 = __expf(v1 - nm);
      v2 = __expf(v2 - nm); v3 = __expf(v3 - nm);
      skP[row*SSTR + tx    ] = v0;
      skP[row*SSTR + tx + 16] = v1;
      skP[row*SSTR + tx + 32] = v2;
      skP[row*SSTR + tx + 48] = v3;
      float ls = v0 + v1 + v2 + v3;
      ls = rowsum16(ls);
      rsum[i] = rsum[i] * al + ls;
      if (tx == 0) alr[row] = al;
    }
    __syncthreads();                              // P + alr visible
    {
      float al0 = alr[rm+g], al1 = alr[rm+g+8];
#pragma unroll
      for (int nt = 0; nt < 4; nt++) {
        acc[nt][0] *= al0; acc[nt][1] *= al0;
        acc[nt][2] *= al1; acc[nt][3] *= al1;
      }
    }
    mma64_AB_acc(acc, skP, sv, rm, cn, g, tg);    // acc += P @ V (tensor)
    __syncthreads();                              // smem free for next chunk
  }
  const size_t pb = (size_t)(bh*8 + ts) * 4096;
#pragma unroll
  for (int nt = 0; nt < 4; nt++) {
    int col = cn + nt*8 + 2*tg;
    *(float2*)&g_NVp[pb + (rm+g  )*64 + col] = make_float2(acc[nt][0], acc[nt][1]);
    *(float2*)&g_NVp[pb + (rm+g+8)*64 + col] = make_float2(acc[nt][2], acc[nt][3]);
  }
  if (tx == 0) {
#pragma unroll
    for (int i = 0; i < 4; i++) {
      g_mp[(bh*8 + ts)*64 + ty + 16*i] = rowm[i];
      g_sp[(bh*8 + ts)*64 + ty + 16*i] = rsum[i];
    }
  }
}

// ---------------- FUSED: Newton-Schulz + combine + Z (scalar, unchanged) ---
__global__ __launch_bounds__(256) void ns_combine_z_kernel() {
  extern __shared__ float sm[];
  float* sK  = sm;
  float* sV  = sm + TILE;
  float* sKV = sm + 2*TILE;
  float* sT  = sm + 3*TILE;
  float* sU  = sm + 4*TILE;
  __shared__ float scol[64];
  __shared__ float sden;
  __shared__ float W[8][64];
  __shared__ float D[64];
  const int bh = blockIdx.x;
  const int tid = threadIdx.x;
  const int ty = tid >> 4, tx = tid & 15;

  tile_load64(sT, g_ql + bh*4096, tid);
  tile_load64(sU, g_kl + bh*4096, tid);
  __syncthreads();
  {
    float acc[4][4];
    mm_regs_ABt(acc, sT, sU, ty, tx);
#pragma unroll
    for (int i = 0; i < 4; i++)
#pragma unroll
      for (int j = 0; j < 4; j++) sK[(ty+16*i)*SSTR + tx + 16*j] = acc[i][j];
  }
  __syncthreads();
  if (tid < 64) {
    float m = -1e30f;
    for (int j = 0; j < 64; j++) m = fmaxf(m, sK[tid*SSTR + j]);
    float s = 0.f;
    for (int j = 0; j < 64; j++) { float e_ = __expf(sK[tid*SSTR + j] - m); sK[tid*SSTR + j] = e_; s += e_; }
    float inv = 1.f / s;
    for (int j = 0; j < 64; j++) sK[tid*SSTR + j] *= inv;
  }
  __syncthreads();
  if (tid < 64) {
    float cs = 0.f;
    for (int i = 0; i < 64; i++) cs += sK[i*SSTR + tid];
    scol[tid] = cs;
  }
  __syncthreads();
  if (tid == 0) {
    float mx = scol[0];
    for (int j = 1; j < 64; j++) mx = fmaxf(mx, scol[j]);
    sden = mx;
  }
  __syncthreads();
  const float invden = 1.f / sden;
  for (int e = tid; e < 4096; e += 256) {
    int i = e >> 6, j = e & 63;
    sV[i*SSTR + j] = sK[j*SSTR + i] * invden;
  }
  __syncthreads();
  for (int it = 0; it < 6; it++) {
    mm_store_AB(sKV, sK, sV, ty, tx); __syncthreads();
    for (int e = tid; e < 4096; e += 256) {
      int i = e >> 6, j = e & 63;
      sT[i*SSTR + j] = ((i == j) ? 7.f : 0.f) - sKV[i*SSTR + j];
    }
    __syncthreads();
    mm_store_AB(sU, sKV, sT, ty, tx); __syncthreads();
    for (int e = tid; e < 4096; e += 256) {
      int i = e >> 6, j = e & 63;
      sT[i*SSTR + j] = ((i == j) ? 15.f : 0.f) - sU[i*SSTR + j];
    }
    __syncthreads();
    mm_store_AB(sU, sKV, sT, ty, tx); __syncthreads();
    for (int e = tid; e < 4096; e += 256) {
      int i = e >> 6, j = e & 63;
      sT[i*SSTR + j] = ((i == j) ? 13.f : 0.f) - sU[i*SSTR + j];
    }
    __syncthreads();
    mm_store_AB(sU, sV, sT, ty, tx); __syncthreads();
    for (int e = tid; e < 4096; e += 256) {
      int i = e >> 6, j = e & 63;
      sV[i*SSTR + j] = 0.25f * sU[i*SSTR + j];
    }
    __syncthreads();
  }
  // combine: NV into sKV
  if (tid < 64) {
    float mp[8];
    float m = -1e30f;
    for (int p = 0; p < 8; p++) { mp[p] = g_mp[(bh*8 + p)*64 + tid]; m = fmaxf(m, mp[p]); }
    float dd = 0.f;
    for (int p = 0; p < 8; p++) {
      float w = __expf(mp[p] - m);
      W[p][tid] = w;
      dd += g_sp[(bh*8 + p)*64 + tid] * w;
    }
    D[tid] = dd;
  }
  __syncthreads();
  for (int e = tid; e < 4096; e += 256) {
    int l = e >> 6, d = e & 63;
    float v = 0.f;
    for (int p = 0; p < 8; p++)
      v += g_NVp[(size_t)(bh*8 + p)*4096 + e] * W[p][l];
    sKV[l*SSTR + d] = v / D[l];
  }
  __syncthreads();
  float acc[4][4];
  mm_regs_AB(acc, sV, sKV, ty, tx);
#pragma unroll
  for (int i = 0; i < 4; i++)
#pragma unroll
    for (int j = 0; j < 4; j++)
      g_Z[bh*4096 + (ty+16*i)*64 + tx + 16*j] = acc[i][j];
}

// ---------------- Y: tensorized S and PZ, rounded + k-permuted -------------
__global__ __launch_bounds__(256) void ly_kernel() {
  extern __shared__ float sm[];
  float* sqP = sm;
  float* skl = sm + TILE;
  float* sZ  = sm + 2*TILE;
  __shared__ float rss[64];
  const int bh = blockIdx.y, tt = blockIdx.x;
  const int tid = threadIdx.x, ty = tid >> 4, tx = tid & 15;
  const int warp = tid >> 5, lane = tid & 31;
  const int g = lane >> 2, tg = lane & 3;
  const int rm = (warp >> 1) * 16, cn = (warp & 1) * 32;
  const int t0 = tt * 64;
  const float* Qb = g_Q + (size_t)bh * HEAD_ELEMS + (size_t)t0 * 64;
  tile_load64(sqP, Qb, tid);
  tile_load64(skl, g_kl + bh*4096, tid);
  tile_load64(sZ,  g_Z  + bh*4096, tid);
  __syncthreads();
  float s[4][4];
  mma64_ABt(s, sqP, skl, rm, cn, g, tg);          // S = q @ k_l^T (tensor)
  __syncthreads();                                 // q reads done
  frag_store(sqP, s, rm, cn, g, tg);               // S -> smem
  __syncthreads();
#pragma unroll
  for (int i = 0; i < 4; i++) {
    const int row = ty + 16*i;
    float v0 = sqP[row*SSTR + tx    ];
    float v1 = sqP[row*SSTR + tx + 16];
    float v2 = sqP[row*SSTR + tx + 32];
    float v3 = sqP[row*SSTR + tx + 48];
    float mx = fmaxf(fmaxf(v0, v1), fmaxf(v2, v3));
    mx = rowmax16(mx);
    v0 = __expf(v0 - mx); v1 = __expf(v1 - mx);
    v2 = __expf(v2 - mx); v3 = __expf(v3 - mx);
    sqP[row*SSTR + tx    ] = v0;
    sqP[row*SSTR + tx + 16] = v1;
    sqP[row*SSTR + tx + 32] = v2;
    sqP[row*SSTR + tx + 48] = v3;
    float ls = v0 + v1 + v2 + v3;
    ls = rowsum16(ls);
    if (tx == 0) rss[row] = ls;
  }
  __syncthreads();                                 // P + rss visible
  float acc[4][4];
#pragma unroll
  for (int nt = 0; nt < 4; nt++)
#pragma unroll
    for (int r = 0; r < 4; r++) acc[nt][r] = 0.f;
  mma64_AB_acc(acc, sqP, sZ, rm, cn, g, tg);       // P @ Z (tensor)
  const int b = bh >> 4, h = bh & 15;
  const float inv0 = 1.f / rss[rm+g], inv1 = 1.f / rss[rm+g+8];
  float* prow0 = g_Y + (size_t)(b*TLEN + t0 + rm + g     ) * CDIM;
  float* prow1 = g_Y + (size_t)(b*TLEN + t0 + rm + g + 8 ) * CDIM;
#pragma unroll
  for (int nt = 0; nt < 4; nt++) {
    int colb = cn + nt*8;                // 8-group base within head
#pragma unroll
    for (int dd = 0; dd < 2; dd++) {
      int w = 2*tg + dd;
      int kpos = 2*(w & 3) + (w >> 2);
      int gcol = h*HS + colb + kpos;
      prow0[gcol] = __uint_as_float(f2tf32(acc[nt][dd    ] * inv0));
      prow1[gcol] = __uint_as_float(f2tf32(acc[nt][dd + 2] * inv1));
    }
  }
}

// ---------------- Launch ----------------
extern "C" void kernel_launch(void* const* d_in, const int* in_sizes, int n_in,
                              void* d_out, int out_size) {
  const float* x  = (const float*)d_in[0];
  const float* Wa = (const float*)d_in[1];
  const float* Wp = (const float*)d_in[2];
  float* out = (float*)d_out;

  const int smem5 = 5 * TILE * 4;
  const int smem3 = 3 * TILE * 4;
  cudaFuncSetAttribute(ns_combine_z_kernel, cudaFuncAttributeMaxDynamicSharedMemorySize, smem5);
  cudaFuncSetAttribute(nv_partial, cudaFuncAttributeMaxDynamicSharedMemorySize, smem3);
  cudaFuncSetAttribute(ly_kernel,  cudaFuncAttributeMaxDynamicSharedMemorySize, smem3);
  cudaFuncSetAttribute((const void*)gemm_tf32<3072,1>, cudaFuncAttributeMaxDynamicSharedMemorySize, GEMM_SMEM);
  cudaFuncSetAttribute((const void*)gemm_tf32<1024,0>, cudaFuncAttributeMaxDynamicSharedMemorySize, GEMM_SMEM);

  float* dX;  cudaGetSymbolAddress((void**)&dX,  g_X);
  float* dWaT; cudaGetSymbolAddress((void**)&dWaT, g_WaT);
  float* dWpT; cudaGetSymbolAddress((void**)&dWpT, g_WpT);
  round_permute_kernel<<<(BATCH*TLEN*CDIM/8 + 255)/256, 256>>>((const float4*)x, (float4*)dX, BATCH*TLEN*CDIM/8);
  transpose_rp_kernel<<<dim3(3*CDIM/32, CDIM/32), 256>>>(Wa, dWaT, 3*CDIM);
  transpose_rp_kernel<<<dim3(CDIM/32, CDIM/32), 256>>>(Wp, dWpT, CDIM);

  gemm_tf32<3072,1><<<dim3(24, 128), 128, GEMM_SMEM>>>(nullptr);
  landmarks_kernel<<<dim3(NLM, BH), 64>>>();
  nv_partial<<<dim3(8, BH), 256, smem3>>>();
  ns_combine_z_kernel<<<BH, 256, smem5>>>();
  ly_kernel<<<dim3(64, BH), 256, smem3>>>();
  gemm_tf32<1024,0><<<dim3(8, 128), 128, GEMM_SMEM>>>(out);
}